// round 4
// baseline (speedup 1.0000x reference)
#include <cuda_runtime.h>

// ---------------- problem constants ----------------
#define BATCH 4
#define SEQ   8192
#define NDIM  512
#define HEADS 8
#define DH    64
#define ML    256          // landmarks
#define LP    32           // tokens per landmark
#define BH    32           // BATCH*HEADS
#define MTOK  32768        // BATCH*SEQ
#define KCONV 33
#define SPLIT 8            // seq split for flash a3v

// ---------------- scratch (device globals; no allocation allowed) ----------------
__device__ float g_q[16777216];      // [BH, SEQ, DH]
__device__ float g_k[16777216];
__device__ float g_v[16777216];
__device__ float g_ql[524288];       // [BH, ML, DH]
__device__ float g_kl[524288];
__device__ float g_attn2[2097152];   // [BH, ML, ML]
__device__ float g_z0[2097152];
__device__ float g_z1[2097152];
__device__ float g_xz[2097152];
__device__ float g_t[2097152];
__device__ float g_u[2097152];
__device__ float g_a3v[524288];      // [BH, ML, DH]
__device__ float g_wm[524288];       // [BH, ML, DH]
__device__ float g_y[16777216];      // [MTOK, NDIM]  (b, n, h*64+dh)
__device__ float g_part_o[4194304];  // [SPLIT][BH*ML][DH]
__device__ float g_part_m[65536];    // [SPLIT][BH*ML]
__device__ float g_part_s[65536];
__device__ float g_scal[2];

// ================= TF32 helpers =================
__device__ __forceinline__ float tf32r(float f)
{
    unsigned u;
    asm("cvt.rna.tf32.f32 %0, %1;" : "=r"(u) : "f"(f));
    return __uint_as_float(u);
}

__device__ __forceinline__ void mma8(float* c, const unsigned* a, unsigned b0, unsigned b1)
{
    asm volatile("mma.sync.aligned.m16n8k8.row.col.f32.tf32.tf32.f32 "
                 "{%0,%1,%2,%3},{%4,%5,%6,%7},{%8,%9},{%0,%1,%2,%3};"
                 : "+f"(c[0]), "+f"(c[1]), "+f"(c[2]), "+f"(c[3])
                 : "r"(a[0]), "r"(a[1]), "r"(a[2]), "r"(a[3]), "r"(b0), "r"(b1));
}

// ================= TF32 tensor-core GEMM (block tile 128x128) =================
// EPI 0: C = alpha*A@B [+bias][+resid]
// EPI 1: optional C = alpha*A@B ; optional D = diag*I - alpha*A@B (batched)
// EPI 2: qkv scatter into g_q/g_k/g_v (q scaled by 0.125)
template<int EPI>
__global__ void __launch_bounds__(256, 2) tgemm_kernel(
    const float* __restrict__ A, const float* __restrict__ B,
    float* __restrict__ C, float* __restrict__ D,
    int K, int lda, int ldb, int ldc,
    long long sA, long long sB, long long sC,
    float alpha, float diag,
    const float* __restrict__ bias, const float* __restrict__ resid)
{
    __shared__ float As[128][20];
    __shared__ float Bs[16][136];

    int bz = blockIdx.z;
    A += bz * sA;
    B += bz * sB;

    const int m0 = blockIdx.y * 128;
    const int n0 = blockIdx.x * 128;
    const int tid = threadIdx.x;
    const int warp = tid >> 5, lane = tid & 31;
    const int gid = lane >> 2, tig = lane & 3;
    const int wm = warp >> 1, wn = warp & 1;

    float acc[2][8][4] = {};

    for (int k0 = 0; k0 < K; k0 += 16) {
        #pragma unroll
        for (int it = 0; it < 2; it++) {
            int idx = tid + it * 256;
            int row = idx >> 2, kq = (idx & 3) << 2;
            float4 v = *(const float4*)&A[(long long)(m0 + row) * lda + k0 + kq];
            float4 w;
            w.x = tf32r(v.x); w.y = tf32r(v.y); w.z = tf32r(v.z); w.w = tf32r(v.w);
            *(float4*)&As[row][kq] = w;
        }
        #pragma unroll
        for (int it = 0; it < 2; it++) {
            int idx = tid + it * 256;
            int row = idx >> 5, nq = (idx & 31) << 2;
            float4 v = *(const float4*)&B[(long long)(k0 + row) * ldb + n0 + nq];
            float4 w;
            w.x = tf32r(v.x); w.y = tf32r(v.y); w.z = tf32r(v.z); w.w = tf32r(v.w);
            *(float4*)&Bs[row][nq] = w;
        }
        __syncthreads();

        #pragma unroll
        for (int s = 0; s < 2; s++) {
            const int kb = s * 8;
            unsigned af[2][4], bf[8][2];
            #pragma unroll
            for (int mf = 0; mf < 2; mf++) {
                int r = wm * 32 + mf * 16 + gid;
                af[mf][0] = __float_as_uint(As[r][kb + tig]);
                af[mf][1] = __float_as_uint(As[r + 8][kb + tig]);
                af[mf][2] = __float_as_uint(As[r][kb + tig + 4]);
                af[mf][3] = __float_as_uint(As[r + 8][kb + tig + 4]);
            }
            #pragma unroll
            for (int nf = 0; nf < 8; nf++) {
                int c = wn * 64 + nf * 8 + gid;
                bf[nf][0] = __float_as_uint(Bs[kb + tig][c]);
                bf[nf][1] = __float_as_uint(Bs[kb + tig + 4][c]);
            }
            #pragma unroll
            for (int mf = 0; mf < 2; mf++)
                #pragma unroll
                for (int nf = 0; nf < 8; nf++)
                    mma8(acc[mf][nf], af[mf], bf[nf][0], bf[nf][1]);
        }
        __syncthreads();
    }

    #pragma unroll
    for (int mf = 0; mf < 2; mf++) {
        #pragma unroll
        for (int nf = 0; nf < 8; nf++) {
            int r0 = m0 + wm * 32 + mf * 16 + gid;
            int c0 = n0 + wn * 64 + nf * 8 + tig * 2;
            float v00 = alpha * acc[mf][nf][0];
            float v01 = alpha * acc[mf][nf][1];
            float v10 = alpha * acc[mf][nf][2];
            float v11 = alpha * acc[mf][nf][3];

            if (EPI == 0) {
                long long o0 = (long long)r0 * ldc + c0;
                long long o1 = (long long)(r0 + 8) * ldc + c0;
                if (bias)  { v00 += bias[c0]; v01 += bias[c0 + 1]; v10 += bias[c0]; v11 += bias[c0 + 1]; }
                if (resid) { v00 += resid[o0]; v01 += resid[o0 + 1]; v10 += resid[o1]; v11 += resid[o1 + 1]; }
                C[o0] = v00; C[o0 + 1] = v01;
                C[o1] = v10; C[o1 + 1] = v11;
            } else if (EPI == 1) {
                long long o0 = bz * sC + (long long)r0 * ldc + c0;
                long long o1 = bz * sC + (long long)(r0 + 8) * ldc + c0;
                if (C) { C[o0] = v00; C[o0 + 1] = v01; C[o1] = v10; C[o1 + 1] = v11; }
                if (D) {
                    D[o0]     = (r0 == c0         ? diag : 0.f) - v00;
                    D[o0 + 1] = (r0 == c0 + 1     ? diag : 0.f) - v01;
                    D[o1]     = (r0 + 8 == c0     ? diag : 0.f) - v10;
                    D[o1 + 1] = (r0 + 8 == c0 + 1 ? diag : 0.f) - v11;
                }
            } else {
                int sec = c0 >> 9;
                int rem = c0 & 511;
                int h = rem >> 6, dh = rem & 63;
                #pragma unroll
                for (int rr = 0; rr < 2; rr++) {
                    int gm = r0 + rr * 8;
                    int b = gm >> 13, n = gm & 8191;
                    long long off = (((long long)(b * HEADS + h)) * SEQ + n) * DH + dh;
                    float a0 = rr ? v10 : v00;
                    float a1 = rr ? v11 : v01;
                    if (sec == 0)      { g_q[off] = a0 * 0.125f; g_q[off + 1] = a1 * 0.125f; }
                    else if (sec == 1) { g_k[off] = a0;          g_k[off + 1] = a1; }
                    else               { g_v[off] = a0;          g_v[off + 1] = a1; }
                }
            }
        }
    }
}

// ---------------- small SIMT GEMM: wm = z @ a3v ----------------
__global__ void gemm_wm_kernel(const float* __restrict__ Zc)
{
    int bz = blockIdx.z;
    const float* A = Zc + (long long)bz * 65536;
    const float* B = g_a3v + (long long)bz * ML * DH;
    float* C = g_wm + (long long)bz * ML * DH;

    __shared__ float As[16][68];
    __shared__ float Bs[16][68];

    const int tid = threadIdx.x;
    const int tx = tid & 15, ty = tid >> 4;
    const int m0 = blockIdx.y * 64;

    float acc[4][4] = {};
    for (int k0 = 0; k0 < ML; k0 += 16) {
        #pragma unroll
        for (int i = tid; i < 1024; i += 256) {
            int m = i >> 4, kk = i & 15;
            As[kk][m] = A[(m0 + m) * ML + k0 + kk];
        }
        #pragma unroll
        for (int i = tid; i < 1024; i += 256) {
            int kk = i >> 6, n = i & 63;
            Bs[kk][n] = B[(k0 + kk) * DH + n];
        }
        __syncthreads();
        #pragma unroll
        for (int kk = 0; kk < 16; kk++) {
            float a[4], bb[4];
            #pragma unroll
            for (int i = 0; i < 4; i++) a[i] = As[kk][ty * 4 + i];
            #pragma unroll
            for (int j = 0; j < 4; j++) bb[j] = Bs[kk][tx * 4 + j];
            #pragma unroll
            for (int i = 0; i < 4; i++)
                #pragma unroll
                for (int j = 0; j < 4; j++)
                    acc[i][j] = fmaf(a[i], bb[j], acc[i][j]);
        }
        __syncthreads();
    }
    #pragma unroll
    for (int i = 0; i < 4; i++)
        #pragma unroll
        for (int j = 0; j < 4; j++)
            C[(m0 + ty * 4 + i) * DH + tx * 4 + j] = acc[i][j];
}

// ---------------- landmark mean pooling ----------------
__global__ void pool_kernel()
{
    long long idx = (long long)blockIdx.x * 256 + threadIdx.x;
    if (idx >= 524288LL) return;
    int dh = idx & 63;
    int mi = (int)((idx >> 6) & 255);
    int bh = (int)(idx >> 14);
    const float* q = g_q + ((long long)bh * SEQ + mi * LP) * DH + dh;
    const float* k = g_k + ((long long)bh * SEQ + mi * LP) * DH + dh;
    float sq = 0.f, sk = 0.f;
    #pragma unroll
    for (int j = 0; j < LP; j++) { sq += q[j * DH]; sk += k[j * DH]; }
    g_ql[idx] = sq * (1.f / LP);
    g_kl[idx] = sk * (1.f / LP);
}

// ---------------- fused attn2 = softmax(ql @ kl^T) (SIMT, tiny) ------------
__global__ void attn2_fused_kernel()
{
    extern __shared__ float sm[];
    float* QsT = sm;            // [64][68]
    float* Bt  = sm + 4352;     // [64][68]
    float* Lg  = sm + 8704;     // [64][260]
    float* inv = sm + 8704 + 16640;  // [64]

    int mt = blockIdx.x;
    int bh = blockIdx.y;
    int tid = threadIdx.x;
    int tx = tid & 15, ty = tid >> 4;

    const float* qlb = g_ql + ((long long)bh * ML + mt * 64) * DH;
    const float* klb = g_kl + (long long)bh * ML * DH;

    for (int i = tid; i < 4096; i += 256) {
        int row = i >> 6, dh = i & 63;
        QsT[dh * 68 + row] = qlb[row * 64 + dh];
    }

    for (int lt = 0; lt < 4; lt++) {
        __syncthreads();
        for (int i = tid; i < 4096; i += 256) {
            int n = i >> 6, dh = i & 63;
            Bt[dh * 68 + n] = klb[(lt * 64 + n) * 64 + dh];
        }
        __syncthreads();
        float s2[4][4] = {};
        #pragma unroll
        for (int kk = 0; kk < 64; kk++) {
            float a[4], b[4];
            #pragma unroll
            for (int i = 0; i < 4; i++) a[i] = QsT[kk * 68 + ty * 4 + i];
            #pragma unroll
            for (int j = 0; j < 4; j++) b[j] = Bt[kk * 68 + tx * 4 + j];
            #pragma unroll
            for (int i = 0; i < 4; i++)
                #pragma unroll
                for (int j = 0; j < 4; j++)
                    s2[i][j] = fmaf(a[i], b[j], s2[i][j]);
        }
        #pragma unroll
        for (int i = 0; i < 4; i++)
            #pragma unroll
            for (int j = 0; j < 4; j++)
                Lg[(ty * 4 + i) * 260 + lt * 64 + tx * 4 + j] = s2[i][j];
    }
    __syncthreads();

    {
        int r = tid >> 2, c0 = (tid & 3) * 64;
        float mx = -1e30f;
        for (int c = 0; c < 64; c++) mx = fmaxf(mx, Lg[r * 260 + c0 + c]);
        mx = fmaxf(mx, __shfl_xor_sync(0xffffffffu, mx, 1));
        mx = fmaxf(mx, __shfl_xor_sync(0xffffffffu, mx, 2));
        float sum = 0.f;
        for (int c = 0; c < 64; c++) {
            float e = __expf(Lg[r * 260 + c0 + c] - mx);
            Lg[r * 260 + c0 + c] = e;
            sum += e;
        }
        sum += __shfl_xor_sync(0xffffffffu, sum, 1);
        sum += __shfl_xor_sync(0xffffffffu, sum, 2);
        if ((tid & 3) == 0) inv[r] = 1.f / sum;
    }
    __syncthreads();

    float* ob = g_attn2 + ((long long)bh * ML + mt * 64) * ML;
    for (int i = tid; i < 16384; i += 256) {
        int row = i >> 8, col = i & 255;
        ob[row * 256 + col] = Lg[row * 260 + col] * inv[row];
    }
}

// ---------------- pinv scale helpers ----------------
__global__ void scale_init_kernel() { if (threadIdx.x < 2) g_scal[threadIdx.x] = 0.f; }

__global__ void pinv_scale_kernel()
{
    int bz = blockIdx.x;
    int j = threadIdx.x;
    const float* p = g_attn2 + (long long)bz * 65536;
    float rs = 0.f, cs = 0.f;
    for (int i = 0; i < 256; i++) { rs += p[j * 256 + i]; cs += p[i * 256 + j]; }
    atomicMax((int*)&g_scal[0], __float_as_int(rs));
    atomicMax((int*)&g_scal[1], __float_as_int(cs));
}

__global__ void zinit_kernel()
{
    long long idx = (long long)blockIdx.x * 256 + threadIdx.x;
    if (idx >= 2097152LL) return;
    float inv = 1.f / (g_scal[0] * g_scal[1]);
    int c = (int)(idx & 255);
    int r = (int)((idx >> 8) & 255);
    long long bz = idx >> 16;
    g_z0[idx] = g_attn2[(bz << 16) + ((long long)c << 8) + r] * inv;
}

// ================= flash a3v (tensor cores) =================
// grid (SPLIT, 4, BH), 256 thr. M=64 landmarks, tiles of 128 seq tokens.
__global__ void __launch_bounds__(256, 1) flash_a3v_tc_kernel()
{
    extern __shared__ float sm[];
    float* Qs  = sm;                 // [64][72]  tf32
    float* Ks  = sm + 4608;          // [128][72] tf32
    float* Vt  = sm + 13824;         // [64][136] tf32 (transposed: [dh][token])
    float* Ss  = sm + 22528;         // [64][136]
    float* msh = sm + 31232;         // [64]
    float* ssh = msh + 64;
    float* fsh = ssh + 64;

    int ks   = blockIdx.x;
    int mt   = blockIdx.y;
    int bh   = blockIdx.z;
    int tid  = threadIdx.x;
    int warp = tid >> 5, lane = tid & 31;
    int gid  = lane >> 2, tig = lane & 3;
    int wm   = warp >> 2, wn = warp & 3;       // 2 x 4 warps

    const float* qlb = g_ql + ((long long)bh * ML + mt * 64) * DH;
    for (int i = tid; i < 4096; i += 256) {
        int row = i >> 6, k = i & 63;
        Qs[row * 72 + k] = tf32r(qlb[row * 64 + k]);
    }
    if (tid < 64) { msh[tid] = -1e30f; ssh[tid] = 0.f; }

    float oacc[2][2][4] = {};
    const float* kb0 = g_k + (long long)bh * SEQ * DH;
    const float* vb0 = g_v + (long long)bh * SEQ * DH;
    int n_beg = ks * (SEQ / SPLIT);

    for (int nt = 0; nt < SEQ / SPLIT; nt += 128) {
        const float* kp = kb0 + (long long)(n_beg + nt) * DH;
        const float* vp = vb0 + (long long)(n_beg + nt) * DH;
        __syncthreads();
        for (int i = tid; i < 8192; i += 256) {
            int t = i >> 6, k = i & 63;
            Ks[t * 72 + k]  = tf32r(kp[t * 64 + k]);
            Vt[k * 136 + t] = tf32r(vp[t * 64 + k]);
        }
        __syncthreads();

        // S[64x128] = Q @ K^T   (warp tile 32x32)
        float sacc[2][4][4] = {};
        #pragma unroll
        for (int s = 0; s < 8; s++) {
            const int kb = s * 8;
            unsigned af[2][4], bf[4][2];
            #pragma unroll
            for (int mf = 0; mf < 2; mf++) {
                int r = wm * 32 + mf * 16 + gid;
                af[mf][0] = __float_as_uint(Qs[r * 72 + kb + tig]);
                af[mf][1] = __float_as_uint(Qs[(r + 8) * 72 + kb + tig]);
                af[mf][2] = __float_as_uint(Qs[r * 72 + kb + tig + 4]);
                af[mf][3] = __float_as_uint(Qs[(r + 8) * 72 + kb + tig + 4]);
            }
            #pragma unroll
            for (int nf = 0; nf < 4; nf++) {
                int n = wn * 32 + nf * 8 + gid;
                bf[nf][0] = __float_as_uint(Ks[n * 72 + kb + tig]);
                bf[nf][1] = __float_as_uint(Ks[n * 72 + kb + tig + 4]);
            }
            #pragma unroll
            for (int mf = 0; mf < 2; mf++)
                #pragma unroll
                for (int nf = 0; nf < 4; nf++)
                    mma8(sacc[mf][nf], af[mf], bf[nf][0], bf[nf][1]);
        }
        #pragma unroll
        for (int mf = 0; mf < 2; mf++)
            #pragma unroll
            for (int nf = 0; nf < 4; nf++) {
                int r = wm * 32 + mf * 16 + gid;
                int c = wn * 32 + nf * 8 + tig * 2;
                Ss[r * 136 + c]           = sacc[mf][nf][0];
                Ss[r * 136 + c + 1]       = sacc[mf][nf][1];
                Ss[(r + 8) * 136 + c]     = sacc[mf][nf][2];
                Ss[(r + 8) * 136 + c + 1] = sacc[mf][nf][3];
            }
        __syncthreads();

        // online softmax (4 threads per row, 32 cols each); P stored tf32
        {
            int r = tid >> 2, c0 = (tid & 3) * 32;
            float mx = -1e30f;
            for (int c = 0; c < 32; c++) mx = fmaxf(mx, Ss[r * 136 + c0 + c]);
            mx = fmaxf(mx, __shfl_xor_sync(0xffffffffu, mx, 1));
            mx = fmaxf(mx, __shfl_xor_sync(0xffffffffu, mx, 2));
            float mold = msh[r];
            float mnew = fmaxf(mold, mx);
            float sum = 0.f;
            for (int c = 0; c < 32; c++) {
                float e = __expf(Ss[r * 136 + c0 + c] - mnew);
                Ss[r * 136 + c0 + c] = tf32r(e);
                sum += e;
            }
            sum += __shfl_xor_sync(0xffffffffu, sum, 1);
            sum += __shfl_xor_sync(0xffffffffu, sum, 2);
            if ((tid & 3) == 0) {
                float f = __expf(mold - mnew);
                ssh[r] = ssh[r] * f + sum;
                msh[r] = mnew;
                fsh[r] = f;
            }
        }
        __syncthreads();

        // oacc = oacc * f(row) + P @ V   (warp tile 32x16, K=128)
        #pragma unroll
        for (int mf = 0; mf < 2; mf++) {
            int r = wm * 32 + mf * 16 + gid;
            float f0 = fsh[r], f1 = fsh[r + 8];
            #pragma unroll
            for (int nf = 0; nf < 2; nf++) {
                oacc[mf][nf][0] *= f0; oacc[mf][nf][1] *= f0;
                oacc[mf][nf][2] *= f1; oacc[mf][nf][3] *= f1;
            }
        }
        #pragma unroll
        for (int s = 0; s < 16; s++) {
            const int kb = s * 8;
            unsigned af[2][4], bf[2][2];
            #pragma unroll
            for (int mf = 0; mf < 2; mf++) {
                int r = wm * 32 + mf * 16 + gid;
                af[mf][0] = __float_as_uint(Ss[r * 136 + kb + tig]);
                af[mf][1] = __float_as_uint(Ss[(r + 8) * 136 + kb + tig]);
                af[mf][2] = __float_as_uint(Ss[r * 136 + kb + tig + 4]);
                af[mf][3] = __float_as_uint(Ss[(r + 8) * 136 + kb + tig + 4]);
            }
            #pragma unroll
            for (int nf = 0; nf < 2; nf++) {
                int n = wn * 16 + nf * 8 + gid;
                bf[nf][0] = __float_as_uint(Vt[n * 136 + kb + tig]);
                bf[nf][1] = __float_as_uint(Vt[n * 136 + kb + tig + 4]);
            }
            #pragma unroll
            for (int mf = 0; mf < 2; mf++)
                #pragma unroll
                for (int nf = 0; nf < 2; nf++)
                    mma8(oacc[mf][nf], af[mf], bf[nf][0], bf[nf][1]);
        }
    }
    __syncthreads();

    float* po = g_part_o + (((long long)ks * BH + bh) * ML + mt * 64) * DH;
    #pragma unroll
    for (int mf = 0; mf < 2; mf++)
        #pragma unroll
        for (int nf = 0; nf < 2; nf++) {
            int r = wm * 32 + mf * 16 + gid;
            int c = wn * 16 + nf * 8 + tig * 2;
            po[r * 64 + c]           = oacc[mf][nf][0];
            po[r * 64 + c + 1]       = oacc[mf][nf][1];
            po[(r + 8) * 64 + c]     = oacc[mf][nf][2];
            po[(r + 8) * 64 + c + 1] = oacc[mf][nf][3];
        }
    if (tid < 64) {
        long long ro = ((long long)ks * BH + bh) * ML + mt * 64 + tid;
        g_part_m[ro] = msh[tid];
        g_part_s[ro] = ssh[tid];
    }
}

// ---------------- merge flash partials into a3v ----------------
__global__ void a3v_merge_kernel()
{
    long long idx = (long long)blockIdx.x * 256 + threadIdx.x;
    if (idx >= 524288LL) return;
    int dh = (int)(idx & 63);
    long long row = idx >> 6;
    float M = -1e30f;
    #pragma unroll
    for (int k = 0; k < SPLIT; k++) M = fmaxf(M, g_part_m[k * 8192 + row]);
    float num = 0.f, den = 0.f;
    #pragma unroll
    for (int k = 0; k < SPLIT; k++) {
        float w = __expf(g_part_m[k * 8192 + row] - M);
        num += g_part_o[(k * 8192 + row) * 64 + dh] * w;
        den += g_part_s[k * 8192 + row] * w;
    }
    g_a3v[idx] = num / den;
}

// ================= attn1 path (tensor cores) + fused conv residual =================
// y[64 tokens x 64 dh] = softmax(q @ kl^T) @ wm + depthwise_conv(v)
// grid (128, BH), 256 thr.
__global__ void __launch_bounds__(256, 1) attn1_out_tc_kernel(const float* __restrict__ convw)
{
    extern __shared__ float sm[];
    float* Qs  = sm;                 // [64][72] tf32   (overlaid by vt later)
    float* Bs  = sm + 4608;          // [64][72] tf32 kl tile (overlaid by vt later)
    float* vt  = sm;                 // [96][64] fp32 conv halo (reuses Qs+Bs region)
    float* Ss  = sm + 9216;          // [64][264]
    float* Wt  = sm + 26112;         // [64][72]  wm^T chunk, tf32
    float* inv = sm + 30720;         // [64]
    float* wsh = sm + 30784;         // [33]

    int st   = blockIdx.x;
    int bh   = blockIdx.y;
    int b    = bh >> 3, h = bh & 7;
    int tid  = threadIdx.x;
    int warp = tid >> 5, lane = tid & 31;
    int gid  = lane >> 2, tig = lane & 3;
    int wm   = warp >> 2, wn = warp & 3;   // 2 x 4 warps

    const float* qb  = g_q  + ((long long)bh * SEQ + st * 64) * DH;
    const float* klb = g_kl + (long long)bh * ML * DH;
    const float* wmb = g_wm + (long long)bh * ML * DH;

    for (int i = tid; i < 4096; i += 256) {
        int row = i >> 6, k = i & 63;
        Qs[row * 72 + k] = tf32r(qb[row * 64 + k]);
    }
    if (tid < KCONV) wsh[tid] = convw[h * KCONV + tid];

    // S[64x256] = Q @ KL^T  (4 chunks of 64 landmarks; warp tile 32x16 per chunk)
    for (int lt = 0; lt < 4; lt++) {
        __syncthreads();
        for (int i = tid; i < 4096; i += 256) {
            int n = i >> 6, k = i & 63;
            Bs[n * 72 + k] = tf32r(klb[(lt * 64 + n) * 64 + k]);
        }
        __syncthreads();
        float sacc[2][2][4] = {};
        #pragma unroll
        for (int s = 0; s < 8; s++) {
            const int kb = s * 8;
            unsigned af[2][4], bf[2][2];
            #pragma unroll
            for (int mf = 0; mf < 2; mf++) {
                int r = wm * 32 + mf * 16 + gid;
                af[mf][0] = __float_as_uint(Qs[r * 72 + kb + tig]);
                af[mf][1] = __float_as_uint(Qs[(r + 8) * 72 + kb + tig]);
                af[mf][2] = __float_as_uint(Qs[r * 72 + kb + tig + 4]);
                af[mf][3] = __float_as_uint(Qs[(r + 8) * 72 + kb + tig + 4]);
            }
            #pragma unroll
            for (int nf = 0; nf < 2; nf++) {
                int n = wn * 16 + nf * 8 + gid;
                bf[nf][0] = __float_as_uint(Bs[n * 72 + kb + tig]);
                bf[nf][1] = __float_as_uint(Bs[n * 72 + kb + tig + 4]);
            }
            #pragma unroll
            for (int mf = 0; mf < 2; mf++)
                #pragma unroll
                for (int nf = 0; nf < 2; nf++)
                    mma8(sacc[mf][nf], af[mf], bf[nf][0], bf[nf][1]);
        }
        #pragma unroll
        for (int mf = 0; mf < 2; mf++)
            #pragma unroll
            for (int nf = 0; nf < 2; nf++) {
                int r = wm * 32 + mf * 16 + gid;
                int c = lt * 64 + wn * 16 + nf * 8 + tig * 2;
                Ss[r * 264 + c]           = sacc[mf][nf][0];
                Ss[r * 264 + c + 1]       = sacc[mf][nf][1];
                Ss[(r + 8) * 264 + c]     = sacc[mf][nf][2];
                Ss[(r + 8) * 264 + c + 1] = sacc[mf][nf][3];
            }
    }
    __syncthreads();

    // softmax rows (256 wide), P = tf32(e / sum)
    {
        int r = tid >> 2, c0 = (tid & 3) * 64;
        float mx = -1e30f;
        for (int c = 0; c < 64; c++) mx = fmaxf(mx, Ss[r * 264 + c0 + c]);
        mx = fmaxf(mx, __shfl_xor_sync(0xffffffffu, mx, 1));
        mx = fmaxf(mx, __shfl_xor_sync(0xffffffffu, mx, 2));
        float sum = 0.f;
        for (int c = 0; c < 64; c++) {
            float e = __expf(Ss[r * 264 + c0 + c] - mx);
            Ss[r * 264 + c0 + c] = e;
            sum += e;
        }
        sum += __shfl_xor_sync(0xffffffffu, sum, 1);
        sum += __shfl_xor_sync(0xffffffffu, sum, 2);
        float iv = 1.f / sum;   // same value in all 4 threads of the row
        for (int c = 0; c < 64; c++)
            Ss[r * 264 + c0 + c] = tf32r(Ss[r * 264 + c0 + c] * iv);
    }
    __syncthreads();

    // conv halo tile: vt[96][64] (overlays Qs/Bs — S phase is complete)
    {
        const float* vbase = g_v + (long long)bh * SEQ * DH;
        int n0 = st * 64;
        for (int i = tid; i < 96 * 64; i += 256) {
            int r = i >> 6, dh = i & 63;
            int n = n0 + r - 16;
            vt[i] = (n >= 0 && n < SEQ) ? vbase[(long long)n * DH + dh] : 0.f;
        }
    }

    // O[64x64] = P @ wm  (4 k-chunks of 64; warp tile 32x16)
    float oacc[2][2][4] = {};
    for (int lt = 0; lt < 4; lt++) {
        __syncthreads();
        for (int i = tid; i < 4096; i += 256) {
            int n = i & 63, kq = i >> 6;
            Wt[n * 72 + kq] = tf32r(wmb[(lt * 64 + kq) * 64 + n]);
        }
        __syncthreads();
        #pragma unroll
        for (int s = 0; s < 8; s++) {
            const int kb = s * 8;
            const int kg = lt * 64 + kb;
            unsigned af[2][4], bf[2][2];
            #pragma unroll
            for (int mf = 0; mf < 2; mf++) {
                int r = wm * 32 + mf * 16 + gid;
                af[mf][0] = __float_as_uint(Ss[r * 264 + kg + tig]);
                af[mf][1] = __float_as_uint(Ss[(r + 8) * 264 + kg + tig]);
                af[mf][2] = __float_as_uint(Ss[r * 264 + kg + tig + 4]);
                af[mf][3] = __float_as_uint(Ss[(r + 8) * 264 + kg + tig + 4]);
            }
            #pragma unroll
            for (int nf = 0; nf < 2; nf++) {
                int n = wn * 16 + nf * 8 + gid;
                bf[nf][0] = __float_as_uint(Wt[n * 72 + kb + tig]);
                bf[nf][1] = __float_as_uint(Wt[n * 72 + kb + tig + 4]);
            }
            #pragma unroll
            for (int mf = 0; mf < 2; mf++)
                #pragma unroll
                for (int nf = 0; nf < 2; nf++)
                    mma8(oacc[mf][nf], af[mf], bf[nf][0], bf[nf][1]);
        }
    }
    __syncthreads();

    // epilogue: y = O + conv(v)
    float* yb = g_y + (((long long)b * SEQ + st * 64) * NDIM) + h * DH;
    #pragma unroll
    for (int mf = 0; mf < 2; mf++)
        #pragma unroll
        for (int nf = 0; nf < 2; nf++) {
            int r = wm * 32 + mf * 16 + gid;
            int c = wn * 16 + nf * 8 + tig * 2;
            float c00 = 0.f, c01 = 0.f, c10 = 0.f, c11 = 0.f;
            #pragma unroll
            for (int t = 0; t < KCONV; t++) {
                float w = wsh[t];
                c00 = fmaf(w, vt[(r + t) * 64 + c], c00);
                c01 = fmaf(w, vt[(r + t) * 64 + c + 1], c01);
                c10 = fmaf(w, vt[(r + 8 + t) * 64 + c], c10);
                c11 = fmaf(w, vt[(r + 8 + t) * 64 + c + 1], c11);
            }
            yb[(long long)r * NDIM + c]           = oacc[mf][nf][0] + c00;
            yb[(long long)r * NDIM + c + 1]       = oacc[mf][nf][1] + c01;
            yb[(long long)(r + 8) * NDIM + c]     = oacc[mf][nf][2] + c10;
            yb[(long long)(r + 8) * NDIM + c + 1] = oacc[mf][nf][3] + c11;
        }
}

// ---------------- host orchestration ----------------
static float* sym(const void* p) { void* a = nullptr; cudaGetSymbolAddress(&a, p); return (float*)a; }

extern "C" void kernel_launch(void* const* d_in, const int* in_sizes, int n_in,
                              void* d_out, int out_size)
{
    const float* x      = (const float*)d_in[0];
    const float* w_qkv  = (const float*)d_in[1];
    const float* w_out  = (const float*)d_in[2];
    const float* b_out  = (const float*)d_in[3];
    const float* conv_w = (const float*)d_in[4];
    float* out = (float*)d_out;

    float* p_a2 = sym(g_attn2);
    float* p_z0 = sym(g_z0);
    float* p_z1 = sym(g_z1);
    float* p_xz = sym(g_xz);
    float* p_t  = sym(g_t);
    float* p_u  = sym(g_u);
    float* p_y  = sym(g_y);

    static int attr_done = 0;
    if (!attr_done) {
        cudaFuncSetAttribute(attn2_fused_kernel,   cudaFuncAttributeMaxDynamicSharedMemorySize, 103000);
        cudaFuncSetAttribute(flash_a3v_tc_kernel,  cudaFuncAttributeMaxDynamicSharedMemorySize, 126500);
        cudaFuncSetAttribute(attn1_out_tc_kernel,  cudaFuncAttributeMaxDynamicSharedMemorySize, 124000);
        attr_done = 1;
    }
    size_t a2_smem = (4352 + 4352 + 16640 + 64) * sizeof(float);     // 101,632
    size_t fl_smem = (31232 + 192) * sizeof(float);                  // 125,696
    size_t a1_smem = (30784 + 40) * sizeof(float);                   // 123,296

    // 1. QKV projection (tensor cores, scatter epilogue)
    tgemm_kernel<2><<<dim3(12, 256, 1), 256>>>(
        x, w_qkv, nullptr, nullptr, 512, 512, 1536, 0,
        0, 0, 0, 1.f, 0.f, nullptr, nullptr);

    // 2. landmark pooling
    pool_kernel<<<2048, 256>>>();

    // 3. attn2 = softmax(ql @ kl^T)
    attn2_fused_kernel<<<dim3(4, BH), 256, a2_smem>>>();

    // 4. pinv init
    scale_init_kernel<<<1, 32>>>();
    pinv_scale_kernel<<<BH, 256>>>();
    zinit_kernel<<<8192, 256>>>();

    // 5. Newton-Schulz iterations (tensor cores, dual-output epilogue)
    float* zc = p_z0;
    float* zn = p_z1;
    for (int it = 0; it < 6; it++) {
        tgemm_kernel<1><<<dim3(2, 2, BH), 256>>>(
            p_a2, zc, p_xz, p_t, 256, 256, 256, 256,
            65536LL, 65536LL, 65536LL, 1.f, 7.f, nullptr, nullptr);
        tgemm_kernel<1><<<dim3(2, 2, BH), 256>>>(
            p_xz, p_t, nullptr, p_u, 256, 256, 256, 256,
            65536LL, 65536LL, 65536LL, 1.f, 15.f, nullptr, nullptr);
        tgemm_kernel<1><<<dim3(2, 2, BH), 256>>>(
            p_xz, p_u, nullptr, p_t, 256, 256, 256, 256,
            65536LL, 65536LL, 65536LL, 1.f, 13.f, nullptr, nullptr);
        tgemm_kernel<1><<<dim3(2, 2, BH), 256>>>(
            zc, p_t, zn, nullptr, 256, 256, 256, 256,
            65536LL, 65536LL, 65536LL, 0.25f, 0.f, nullptr, nullptr);
        float* tmp = zc; zc = zn; zn = tmp;
    }

    // 6. a3v = softmax(ql @ k^T) @ v   (flash, tensor cores)
    flash_a3v_tc_kernel<<<dim3(SPLIT, 4, BH), 256, fl_smem>>>();
    a3v_merge_kernel<<<2048, 256>>>();

    // 7. wm = z @ a3v
    gemm_wm_kernel<<<dim3(1, 4, BH), 256>>>(zc);

    // 8. y = softmax(q @ kl^T) @ wm + conv(v)   (tensor cores, fused conv)
    attn1_out_tc_kernel<<<dim3(128, BH), 256, a1_smem>>>(conv_w);

    // 9. out = y @ w_out + b_out + x   (tensor cores)
    tgemm_kernel<0><<<dim3(4, 256, 1), 256>>>(
        p_y, w_out, out, nullptr, 512, 512, 512, 512,
        0, 0, 0, 1.f, 0.f, b_out, x);
}

// round 5
// speedup vs baseline: 1.4428x; 1.4428x over previous
#include <cuda_runtime.h>

// ---------------- problem constants ----------------
#define BATCH 4
#define SEQ   8192
#define NDIM  512
#define HEADS 8
#define DH    64
#define ML    256          // landmarks
#define LP    32           // tokens per landmark
#define BH    32           // BATCH*HEADS
#define MTOK  32768        // BATCH*SEQ
#define KCONV 33
#define SPLIT 8            // seq split for flash a3v

// ---------------- scratch (device globals; no allocation allowed) ----------------
__device__ float g_q[16777216];      // [BH, SEQ, DH]
__device__ float g_k[16777216];
__device__ float g_v[16777216];
__device__ float g_ql[524288];       // [BH, ML, DH]
__device__ float g_kl[524288];
__device__ float g_attn2[2097152];   // [BH, ML, ML]
__device__ float g_z0[2097152];
__device__ float g_z1[2097152];
__device__ float g_xz[2097152];
__device__ float g_t[2097152];
__device__ float g_u[2097152];
__device__ float g_a3v[524288];      // [BH, ML, DH]
__device__ float g_wm[524288];       // [BH, ML, DH]
__device__ float g_y[16777216];      // [MTOK, NDIM]  (b, n, h*64+dh)
__device__ float g_part_o[4194304];  // [SPLIT][BH*ML][DH]
__device__ float g_part_m[65536];    // [SPLIT][BH*ML]
__device__ float g_part_s[65536];
__device__ float g_scal[2] = {0.f, 0.f};   // atomicMax is idempotent across replays

// ================= TF32 helpers =================
__device__ __forceinline__ float tf32r(float f)
{
    unsigned u;
    asm("cvt.rna.tf32.f32 %0, %1;" : "=r"(u) : "f"(f));
    return __uint_as_float(u);
}

__device__ __forceinline__ float4 tf32r4(float4 v)
{
    float4 w;
    w.x = tf32r(v.x); w.y = tf32r(v.y); w.z = tf32r(v.z); w.w = tf32r(v.w);
    return w;
}

__device__ __forceinline__ void mma8(float* c, const unsigned* a, unsigned b0, unsigned b1)
{
    asm volatile("mma.sync.aligned.m16n8k8.row.col.f32.tf32.tf32.f32 "
                 "{%0,%1,%2,%3},{%4,%5,%6,%7},{%8,%9},{%0,%1,%2,%3};"
                 : "+f"(c[0]), "+f"(c[1]), "+f"(c[2]), "+f"(c[3])
                 : "r"(a[0]), "r"(a[1]), "r"(a[2]), "r"(a[3]), "r"(b0), "r"(b1));
}

// ================= TF32 tensor-core GEMM (block tile 128x128) =================
// EPI 0: C = alpha*A@B [+bias][+resid]
// EPI 1: optional C = alpha*A@B ; optional D = diag*I - alpha*A@B (batched)
// EPI 2: qkv scatter into g_q/g_k/g_v (q scaled by 0.125)
template<int EPI>
__global__ void __launch_bounds__(256, 2) tgemm_kernel(
    const float* __restrict__ A, const float* __restrict__ B,
    float* __restrict__ C, float* __restrict__ D,
    int K, int lda, int ldb, int ldc,
    long long sA, long long sB, long long sC,
    float alpha, float diag,
    const float* __restrict__ bias, const float* __restrict__ resid)
{
    __shared__ float As[128][20];
    __shared__ float Bs[16][136];

    int bz = blockIdx.z;
    A += bz * sA;
    B += bz * sB;

    const int m0 = blockIdx.y * 128;
    const int n0 = blockIdx.x * 128;
    const int tid = threadIdx.x;
    const int warp = tid >> 5, lane = tid & 31;
    const int gid = lane >> 2, tig = lane & 3;
    const int wm = warp >> 1, wn = warp & 1;

    float acc[2][8][4] = {};

    for (int k0 = 0; k0 < K; k0 += 16) {
        #pragma unroll
        for (int it = 0; it < 2; it++) {
            int idx = tid + it * 256;
            int row = idx >> 2, kq = (idx & 3) << 2;
            float4 v = *(const float4*)&A[(long long)(m0 + row) * lda + k0 + kq];
            *(float4*)&As[row][kq] = tf32r4(v);
        }
        #pragma unroll
        for (int it = 0; it < 2; it++) {
            int idx = tid + it * 256;
            int row = idx >> 5, nq = (idx & 31) << 2;
            float4 v = *(const float4*)&B[(long long)(k0 + row) * ldb + n0 + nq];
            *(float4*)&Bs[row][nq] = tf32r4(v);
        }
        __syncthreads();

        #pragma unroll
        for (int s = 0; s < 2; s++) {
            const int kb = s * 8;
            unsigned af[2][4], bf[8][2];
            #pragma unroll
            for (int mf = 0; mf < 2; mf++) {
                int r = wm * 32 + mf * 16 + gid;
                af[mf][0] = __float_as_uint(As[r][kb + tig]);
                af[mf][1] = __float_as_uint(As[r + 8][kb + tig]);
                af[mf][2] = __float_as_uint(As[r][kb + tig + 4]);
                af[mf][3] = __float_as_uint(As[r + 8][kb + tig + 4]);
            }
            #pragma unroll
            for (int nf = 0; nf < 8; nf++) {
                int c = wn * 64 + nf * 8 + gid;
                bf[nf][0] = __float_as_uint(Bs[kb + tig][c]);
                bf[nf][1] = __float_as_uint(Bs[kb + tig + 4][c]);
            }
            #pragma unroll
            for (int mf = 0; mf < 2; mf++)
                #pragma unroll
                for (int nf = 0; nf < 8; nf++)
                    mma8(acc[mf][nf], af[mf], bf[nf][0], bf[nf][1]);
        }
        __syncthreads();
    }

    #pragma unroll
    for (int mf = 0; mf < 2; mf++) {
        #pragma unroll
        for (int nf = 0; nf < 8; nf++) {
            int r0 = m0 + wm * 32 + mf * 16 + gid;
            int c0 = n0 + wn * 64 + nf * 8 + tig * 2;
            float v00 = alpha * acc[mf][nf][0];
            float v01 = alpha * acc[mf][nf][1];
            float v10 = alpha * acc[mf][nf][2];
            float v11 = alpha * acc[mf][nf][3];

            if (EPI == 0) {
                long long o0 = (long long)r0 * ldc + c0;
                long long o1 = (long long)(r0 + 8) * ldc + c0;
                if (bias)  { v00 += bias[c0]; v01 += bias[c0 + 1]; v10 += bias[c0]; v11 += bias[c0 + 1]; }
                if (resid) { v00 += resid[o0]; v01 += resid[o0 + 1]; v10 += resid[o1]; v11 += resid[o1 + 1]; }
                C[o0] = v00; C[o0 + 1] = v01;
                C[o1] = v10; C[o1 + 1] = v11;
            } else if (EPI == 1) {
                long long o0 = bz * sC + (long long)r0 * ldc + c0;
                long long o1 = bz * sC + (long long)(r0 + 8) * ldc + c0;
                if (C) { C[o0] = v00; C[o0 + 1] = v01; C[o1] = v10; C[o1 + 1] = v11; }
                if (D) {
                    D[o0]     = (r0 == c0         ? diag : 0.f) - v00;
                    D[o0 + 1] = (r0 == c0 + 1     ? diag : 0.f) - v01;
                    D[o1]     = (r0 + 8 == c0     ? diag : 0.f) - v10;
                    D[o1 + 1] = (r0 + 8 == c0 + 1 ? diag : 0.f) - v11;
                }
            } else {
                int sec = c0 >> 9;
                int rem = c0 & 511;
                int h = rem >> 6, dh = rem & 63;
                #pragma unroll
                for (int rr = 0; rr < 2; rr++) {
                    int gm = r0 + rr * 8;
                    int b = gm >> 13, n = gm & 8191;
                    long long off = (((long long)(b * HEADS + h)) * SEQ + n) * DH + dh;
                    float a0 = rr ? v10 : v00;
                    float a1 = rr ? v11 : v01;
                    if (sec == 0)      { g_q[off] = a0 * 0.125f; g_q[off + 1] = a1 * 0.125f; }
                    else if (sec == 1) { g_k[off] = a0;          g_k[off + 1] = a1; }
                    else               { g_v[off] = a0;          g_v[off + 1] = a1; }
                }
            }
        }
    }
}

// ---------------- small SIMT GEMM: wm = z @ a3v ----------------
__global__ void gemm_wm_kernel(const float* __restrict__ Zc)
{
    int bz = blockIdx.z;
    const float* A = Zc + (long long)bz * 65536;
    const float* B = g_a3v + (long long)bz * ML * DH;
    float* C = g_wm + (long long)bz * ML * DH;

    __shared__ float As[16][68];
    __shared__ float Bs[16][68];

    const int tid = threadIdx.x;
    const int tx = tid & 15, ty = tid >> 4;
    const int m0 = blockIdx.y * 64;

    float acc[4][4] = {};
    for (int k0 = 0; k0 < ML; k0 += 16) {
        #pragma unroll
        for (int i = tid; i < 1024; i += 256) {
            int m = i >> 4, kk = i & 15;
            As[kk][m] = A[(m0 + m) * ML + k0 + kk];
        }
        #pragma unroll
        for (int i = tid; i < 1024; i += 256) {
            int kk = i >> 6, n = i & 63;
            Bs[kk][n] = B[(k0 + kk) * DH + n];
        }
        __syncthreads();
        #pragma unroll
        for (int kk = 0; kk < 16; kk++) {
            float a[4], bb[4];
            #pragma unroll
            for (int i = 0; i < 4; i++) a[i] = As[kk][ty * 4 + i];
            #pragma unroll
            for (int j = 0; j < 4; j++) bb[j] = Bs[kk][tx * 4 + j];
            #pragma unroll
            for (int i = 0; i < 4; i++)
                #pragma unroll
                for (int j = 0; j < 4; j++)
                    acc[i][j] = fmaf(a[i], bb[j], acc[i][j]);
        }
        __syncthreads();
    }
    #pragma unroll
    for (int i = 0; i < 4; i++)
        #pragma unroll
        for (int j = 0; j < 4; j++)
            C[(m0 + ty * 4 + i) * DH + tx * 4 + j] = acc[i][j];
}

// ---------------- landmark mean pooling ----------------
__global__ void pool_kernel()
{
    long long idx = (long long)blockIdx.x * 256 + threadIdx.x;
    if (idx >= 524288LL) return;
    int dh = idx & 63;
    int mi = (int)((idx >> 6) & 255);
    int bh = (int)(idx >> 14);
    const float* q = g_q + ((long long)bh * SEQ + mi * LP) * DH + dh;
    const float* k = g_k + ((long long)bh * SEQ + mi * LP) * DH + dh;
    float sq = 0.f, sk = 0.f;
    #pragma unroll
    for (int j = 0; j < LP; j++) { sq += q[j * DH]; sk += k[j * DH]; }
    g_ql[idx] = sq * (1.f / LP);
    g_kl[idx] = sk * (1.f / LP);
}

// ---------------- fused attn2 = softmax(ql @ kl^T) (SIMT, tiny) ------------
__global__ void attn2_fused_kernel()
{
    extern __shared__ float sm[];
    float* QsT = sm;            // [64][68]
    float* Bt  = sm + 4352;     // [64][68]
    float* Lg  = sm + 8704;     // [64][260]
    float* inv = sm + 8704 + 16640;  // [64]

    int mt = blockIdx.x;
    int bh = blockIdx.y;
    int tid = threadIdx.x;
    int tx = tid & 15, ty = tid >> 4;

    const float* qlb = g_ql + ((long long)bh * ML + mt * 64) * DH;
    const float* klb = g_kl + (long long)bh * ML * DH;

    for (int i = tid; i < 4096; i += 256) {
        int row = i >> 6, dh = i & 63;
        QsT[dh * 68 + row] = qlb[row * 64 + dh];
    }

    for (int lt = 0; lt < 4; lt++) {
        __syncthreads();
        for (int i = tid; i < 4096; i += 256) {
            int n = i >> 6, dh = i & 63;
            Bt[dh * 68 + n] = klb[(lt * 64 + n) * 64 + dh];
        }
        __syncthreads();
        float s2[4][4] = {};
        #pragma unroll
        for (int kk = 0; kk < 64; kk++) {
            float a[4], b[4];
            #pragma unroll
            for (int i = 0; i < 4; i++) a[i] = QsT[kk * 68 + ty * 4 + i];
            #pragma unroll
            for (int j = 0; j < 4; j++) b[j] = Bt[kk * 68 + tx * 4 + j];
            #pragma unroll
            for (int i = 0; i < 4; i++)
                #pragma unroll
                for (int j = 0; j < 4; j++)
                    s2[i][j] = fmaf(a[i], b[j], s2[i][j]);
        }
        #pragma unroll
        for (int i = 0; i < 4; i++)
            #pragma unroll
            for (int j = 0; j < 4; j++)
                Lg[(ty * 4 + i) * 260 + lt * 64 + tx * 4 + j] = s2[i][j];
    }
    __syncthreads();

    {
        int r = tid >> 2, c0 = (tid & 3) * 64;
        float mx = -1e30f;
        for (int c = 0; c < 64; c++) mx = fmaxf(mx, Lg[r * 260 + c0 + c]);
        mx = fmaxf(mx, __shfl_xor_sync(0xffffffffu, mx, 1));
        mx = fmaxf(mx, __shfl_xor_sync(0xffffffffu, mx, 2));
        float sum = 0.f;
        for (int c = 0; c < 64; c++) {
            float e = __expf(Lg[r * 260 + c0 + c] - mx);
            Lg[r * 260 + c0 + c] = e;
            sum += e;
        }
        sum += __shfl_xor_sync(0xffffffffu, sum, 1);
        sum += __shfl_xor_sync(0xffffffffu, sum, 2);
        if ((tid & 3) == 0) inv[r] = 1.f / sum;
    }
    __syncthreads();

    float* ob = g_attn2 + ((long long)bh * ML + mt * 64) * ML;
    for (int i = tid; i < 16384; i += 256) {
        int row = i >> 8, col = i & 255;
        ob[row * 256 + col] = Lg[row * 260 + col] * inv[row];
    }
}

// ---------------- pinv scale + z init ----------------
__global__ void pinv_scale_kernel()
{
    int bz = blockIdx.x;
    int j = threadIdx.x;
    const float* p = g_attn2 + (long long)bz * 65536;
    float rs = 0.f, cs = 0.f;
    for (int i = 0; i < 256; i++) { rs += p[j * 256 + i]; cs += p[i * 256 + j]; }
    atomicMax((int*)&g_scal[0], __float_as_int(rs));
    atomicMax((int*)&g_scal[1], __float_as_int(cs));
}

__global__ void zinit_kernel()
{
    long long idx = (long long)blockIdx.x * 256 + threadIdx.x;
    if (idx >= 2097152LL) return;
    float inv = 1.f / (g_scal[0] * g_scal[1]);
    int c = (int)(idx & 255);
    int r = (int)((idx >> 8) & 255);
    long long bz = idx >> 16;
    g_z0[idx] = g_attn2[(bz << 16) + ((long long)c << 8) + r] * inv;
}

// ================= flash a3v (tensor cores, v2) =================
// grid (SPLIT, 4, BH), 256 thr, 2 blocks/SM. 64 landmark rows x 128-token tiles.
// smem: Qs[64][68] | Ks[128][68] (overlaid by Ss[64][132] after QK) | Vs[128][68] | m/s/f
__global__ void __launch_bounds__(256, 2) flash_a3v_tc_kernel()
{
    extern __shared__ float sm[];
    float* Qs  = sm;                 // 4352
    float* Ks  = sm + 4352;          // 8704  (tokens x k)
    float* Ss  = sm + 4352;          // 8448  (overlay, after QK mma)
    float* Vs  = sm + 13056;         // 8704  (tokens x dh)  = natural B layout for P@V
    float* msh = sm + 21760;         // 64
    float* ssh = msh + 64;
    float* fsh = ssh + 64;

    int ks   = blockIdx.x;
    int mt   = blockIdx.y;
    int bh   = blockIdx.z;
    int tid  = threadIdx.x;
    int warp = tid >> 5, lane = tid & 31;
    int gid  = lane >> 2, tig = lane & 3;
    int wm   = warp >> 2, wn = warp & 3;       // 2 x 4 warps

    const float* qlb = g_ql + ((long long)bh * ML + mt * 64) * DH;
    // stage Q (float4): 64x64 = 1024 float4
    for (int i = tid; i < 1024; i += 256) {
        int row = i >> 4, kq = (i & 15) << 2;
        float4 v = *(const float4*)&qlb[row * 64 + kq];
        *(float4*)&Qs[row * 68 + kq] = tf32r4(v);
    }
    if (tid < 64) { msh[tid] = -1e30f; ssh[tid] = 0.f; }

    float oacc[2][2][4] = {};
    const float* kb0 = g_k + (long long)bh * SEQ * DH;
    const float* vb0 = g_v + (long long)bh * SEQ * DH;
    int n_beg = ks * (SEQ / SPLIT);

    for (int nt = 0; nt < SEQ / SPLIT; nt += 128) {
        const float* kp = kb0 + (long long)(n_beg + nt) * DH;
        const float* vp = vb0 + (long long)(n_beg + nt) * DH;
        __syncthreads();                       // prior PV reads of Ss/Vs done
        // stage K,V tiles: 128x64 each = 2048 float4 each
        for (int i = tid; i < 2048; i += 256) {
            int t = i >> 4, kq = (i & 15) << 2;
            float4 kv = *(const float4*)&kp[t * 64 + kq];
            float4 vv = *(const float4*)&vp[t * 64 + kq];
            *(float4*)&Ks[t * 68 + kq] = tf32r4(kv);
            *(float4*)&Vs[t * 68 + kq] = tf32r4(vv);
        }
        __syncthreads();

        // S[64x128] = Q @ K^T   (warp tile 32x32)
        float sacc[2][4][4] = {};
        #pragma unroll
        for (int s = 0; s < 8; s++) {
            const int kb = s * 8;
            unsigned af[2][4], bf[4][2];
            #pragma unroll
            for (int mf = 0; mf < 2; mf++) {
                int r = wm * 32 + mf * 16 + gid;
                af[mf][0] = __float_as_uint(Qs[r * 68 + kb + tig]);
                af[mf][1] = __float_as_uint(Qs[(r + 8) * 68 + kb + tig]);
                af[mf][2] = __float_as_uint(Qs[r * 68 + kb + tig + 4]);
                af[mf][3] = __float_as_uint(Qs[(r + 8) * 68 + kb + tig + 4]);
            }
            #pragma unroll
            for (int nf = 0; nf < 4; nf++) {
                int n = wn * 32 + nf * 8 + gid;
                bf[nf][0] = __float_as_uint(Ks[n * 68 + kb + tig]);
                bf[nf][1] = __float_as_uint(Ks[n * 68 + kb + tig + 4]);
            }
            #pragma unroll
            for (int mf = 0; mf < 2; mf++)
                #pragma unroll
                for (int nf = 0; nf < 4; nf++)
                    mma8(sacc[mf][nf], af[mf], bf[nf][0], bf[nf][1]);
        }
        __syncthreads();                        // Ks reads complete; Ss overlay safe

        #pragma unroll
        for (int mf = 0; mf < 2; mf++)
            #pragma unroll
            for (int nf = 0; nf < 4; nf++) {
                int r = wm * 32 + mf * 16 + gid;
                int c = wn * 32 + nf * 8 + tig * 2;
                Ss[r * 132 + c]           = sacc[mf][nf][0];
                Ss[r * 132 + c + 1]       = sacc[mf][nf][1];
                Ss[(r + 8) * 132 + c]     = sacc[mf][nf][2];
                Ss[(r + 8) * 132 + c + 1] = sacc[mf][nf][3];
            }
        __syncthreads();

        // online softmax: 4 threads/row, float4 over 32 cols each; P stored tf32
        {
            int r = tid >> 2;
            float4* rp = (float4*)&Ss[r * 132 + (tid & 3) * 32];
            float mx = -1e30f;
            #pragma unroll
            for (int i = 0; i < 8; i++) {
                float4 v = rp[i];
                mx = fmaxf(mx, fmaxf(fmaxf(v.x, v.y), fmaxf(v.z, v.w)));
            }
            mx = fmaxf(mx, __shfl_xor_sync(0xffffffffu, mx, 1));
            mx = fmaxf(mx, __shfl_xor_sync(0xffffffffu, mx, 2));
            float mold = msh[r];
            float mnew = fmaxf(mold, mx);
            float sum = 0.f;
            #pragma unroll
            for (int i = 0; i < 8; i++) {
                float4 v = rp[i];
                v.x = __expf(v.x - mnew); v.y = __expf(v.y - mnew);
                v.z = __expf(v.z - mnew); v.w = __expf(v.w - mnew);
                sum += (v.x + v.y) + (v.z + v.w);
                rp[i] = tf32r4(v);
            }
            sum += __shfl_xor_sync(0xffffffffu, sum, 1);
            sum += __shfl_xor_sync(0xffffffffu, sum, 2);
            if ((tid & 3) == 0) {
                float f = __expf(mold - mnew);
                ssh[r] = ssh[r] * f + sum;
                msh[r] = mnew;
                fsh[r] = f;
            }
        }
        __syncthreads();

        // oacc = oacc * f(row) + P @ V   (warp tile 32x16, K=128)
        #pragma unroll
        for (int mf = 0; mf < 2; mf++) {
            int r = wm * 32 + mf * 16 + gid;
            float f0 = fsh[r], f1 = fsh[r + 8];
            #pragma unroll
            for (int nf = 0; nf < 2; nf++) {
                oacc[mf][nf][0] *= f0; oacc[mf][nf][1] *= f0;
                oacc[mf][nf][2] *= f1; oacc[mf][nf][3] *= f1;
            }
        }
        #pragma unroll
        for (int s = 0; s < 16; s++) {
            const int kb = s * 8;
            unsigned af[2][4], bf[2][2];
            #pragma unroll
            for (int mf = 0; mf < 2; mf++) {
                int r = wm * 32 + mf * 16 + gid;
                af[mf][0] = __float_as_uint(Ss[r * 132 + kb + tig]);
                af[mf][1] = __float_as_uint(Ss[(r + 8) * 132 + kb + tig]);
                af[mf][2] = __float_as_uint(Ss[r * 132 + kb + tig + 4]);
                af[mf][3] = __float_as_uint(Ss[(r + 8) * 132 + kb + tig + 4]);
            }
            #pragma unroll
            for (int nf = 0; nf < 2; nf++) {
                int n = wn * 16 + nf * 8 + gid;
                bf[nf][0] = __float_as_uint(Vs[(kb + tig) * 68 + n]);
                bf[nf][1] = __float_as_uint(Vs[(kb + tig + 4) * 68 + n]);
            }
            #pragma unroll
            for (int mf = 0; mf < 2; mf++)
                #pragma unroll
                for (int nf = 0; nf < 2; nf++)
                    mma8(oacc[mf][nf], af[mf], bf[nf][0], bf[nf][1]);
        }
    }
    __syncthreads();

    float* po = g_part_o + (((long long)ks * BH + bh) * ML + mt * 64) * DH;
    #pragma unroll
    for (int mf = 0; mf < 2; mf++)
        #pragma unroll
        for (int nf = 0; nf < 2; nf++) {
            int r = wm * 32 + mf * 16 + gid;
            int c = wn * 16 + nf * 8 + tig * 2;
            po[r * 64 + c]           = oacc[mf][nf][0];
            po[r * 64 + c + 1]       = oacc[mf][nf][1];
            po[(r + 8) * 64 + c]     = oacc[mf][nf][2];
            po[(r + 8) * 64 + c + 1] = oacc[mf][nf][3];
        }
    if (tid < 64) {
        long long ro = ((long long)ks * BH + bh) * ML + mt * 64 + tid;
        g_part_m[ro] = msh[tid];
        g_part_s[ro] = ssh[tid];
    }
}

// ---------------- merge flash partials into a3v ----------------
__global__ void a3v_merge_kernel()
{
    long long idx = (long long)blockIdx.x * 256 + threadIdx.x;
    if (idx >= 524288LL) return;
    int dh = (int)(idx & 63);
    long long row = idx >> 6;
    float M = -1e30f;
    #pragma unroll
    for (int k = 0; k < SPLIT; k++) M = fmaxf(M, g_part_m[k * 8192 + row]);
    float num = 0.f, den = 0.f;
    #pragma unroll
    for (int k = 0; k < SPLIT; k++) {
        float w = __expf(g_part_m[k * 8192 + row] - M);
        num += g_part_o[(k * 8192 + row) * 64 + dh] * w;
        den += g_part_s[k * 8192 + row] * w;
    }
    g_a3v[idx] = num / den;
}

// ================= attn1 path (tensor cores, v2) + fused conv =================
// y[64 tok x 64 dh] = softmax(q @ kl^T) @ wm + depthwise_conv(v)
// grid (128, BH), 256 thr, 2 blocks/SM.
// smem: Qs[64][68] (overlaid by Wt) | Bs[64][68] | Ss[64][260] (overlaid by vt[96][64]) | inv | wsh
__global__ void __launch_bounds__(256, 2) attn1_out_tc_kernel(const float* __restrict__ convw)
{
    extern __shared__ float sm[];
    float* Qs  = sm;                 // 4352
    float* Wt  = sm;                 // overlay (after S phase): [64 k][68] wm chunk
    float* Bs  = sm + 4352;          // 4352
    float* Ss  = sm + 8704;          // 16640 = [64][260]
    float* vt  = sm + 8704;          // overlay (after PV): [96][64] conv halo
    float* inv = sm + 25344;         // 64
    float* wsh = sm + 25408;         // 33

    int st   = blockIdx.x;
    int bh   = blockIdx.y;
    int b    = bh >> 3, h = bh & 7;
    int tid  = threadIdx.x;
    int warp = tid >> 5, lane = tid & 31;
    int gid  = lane >> 2, tig = lane & 3;
    int wm   = warp >> 2, wn = warp & 3;   // 2 x 4 warps

    const float* qb  = g_q  + ((long long)bh * SEQ + st * 64) * DH;
    const float* klb = g_kl + (long long)bh * ML * DH;
    const float* wmb = g_wm + (long long)bh * ML * DH;

    for (int i = tid; i < 1024; i += 256) {
        int row = i >> 4, kq = (i & 15) << 2;
        float4 v = *(const float4*)&qb[row * 64 + kq];
        *(float4*)&Qs[row * 68 + kq] = tf32r4(v);
    }
    if (tid < KCONV) wsh[tid] = convw[h * KCONV + tid];

    // S[64x256] = Q @ KL^T  (4 chunks of 64 landmarks; warp tile 32x16)
    for (int lt = 0; lt < 4; lt++) {
        __syncthreads();
        for (int i = tid; i < 1024; i += 256) {
            int n = i >> 4, kq = (i & 15) << 2;
            float4 v = *(const float4*)&klb[(lt * 64 + n) * 64 + kq];
            *(float4*)&Bs[n * 68 + kq] = tf32r4(v);
        }
        __syncthreads();
        float sacc[2][2][4] = {};
        #pragma unroll
        for (int s = 0; s < 8; s++) {
            const int kb = s * 8;
            unsigned af[2][4], bf[2][2];
            #pragma unroll
            for (int mf = 0; mf < 2; mf++) {
                int r = wm * 32 + mf * 16 + gid;
                af[mf][0] = __float_as_uint(Qs[r * 68 + kb + tig]);
                af[mf][1] = __float_as_uint(Qs[(r + 8) * 68 + kb + tig]);
                af[mf][2] = __float_as_uint(Qs[r * 68 + kb + tig + 4]);
                af[mf][3] = __float_as_uint(Qs[(r + 8) * 68 + kb + tig + 4]);
            }
            #pragma unroll
            for (int nf = 0; nf < 2; nf++) {
                int n = wn * 16 + nf * 8 + gid;
                bf[nf][0] = __float_as_uint(Bs[n * 68 + kb + tig]);
                bf[nf][1] = __float_as_uint(Bs[n * 68 + kb + tig + 4]);
            }
            #pragma unroll
            for (int mf = 0; mf < 2; mf++)
                #pragma unroll
                for (int nf = 0; nf < 2; nf++)
                    mma8(sacc[mf][nf], af[mf], bf[nf][0], bf[nf][1]);
        }
        #pragma unroll
        for (int mf = 0; mf < 2; mf++)
            #pragma unroll
            for (int nf = 0; nf < 2; nf++) {
                int r = wm * 32 + mf * 16 + gid;
                int c = lt * 64 + wn * 16 + nf * 8 + tig * 2;
                Ss[r * 260 + c]           = sacc[mf][nf][0];
                Ss[r * 260 + c + 1]       = sacc[mf][nf][1];
                Ss[(r + 8) * 260 + c]     = sacc[mf][nf][2];
                Ss[(r + 8) * 260 + c + 1] = sacc[mf][nf][3];
            }
    }
    __syncthreads();

    // softmax rows (256 wide, float4): store tf32(e); 1/sum applied at epilogue
    {
        int r = tid >> 2;
        float4* rp = (float4*)&Ss[r * 260 + (tid & 3) * 64];
        float mx = -1e30f;
        #pragma unroll
        for (int i = 0; i < 16; i++) {
            float4 v = rp[i];
            mx = fmaxf(mx, fmaxf(fmaxf(v.x, v.y), fmaxf(v.z, v.w)));
        }
        mx = fmaxf(mx, __shfl_xor_sync(0xffffffffu, mx, 1));
        mx = fmaxf(mx, __shfl_xor_sync(0xffffffffu, mx, 2));
        float sum = 0.f;
        #pragma unroll
        for (int i = 0; i < 16; i++) {
            float4 v = rp[i];
            v.x = __expf(v.x - mx); v.y = __expf(v.y - mx);
            v.z = __expf(v.z - mx); v.w = __expf(v.w - mx);
            sum += (v.x + v.y) + (v.z + v.w);
            rp[i] = tf32r4(v);
        }
        sum += __shfl_xor_sync(0xffffffffu, sum, 1);
        sum += __shfl_xor_sync(0xffffffffu, sum, 2);
        if ((tid & 3) == 0) inv[r] = 1.f / sum;
    }
    __syncthreads();

    // O[64x64] = P @ wm  (4 k-chunks; Wt overlays Qs; B in natural [k][n] layout)
    float oacc[2][2][4] = {};
    for (int lt = 0; lt < 4; lt++) {
        __syncthreads();
        for (int i = tid; i < 1024; i += 256) {
            int kq = i >> 4, nq = (i & 15) << 2;
            float4 v = *(const float4*)&wmb[(lt * 64 + kq) * 64 + nq];
            *(float4*)&Wt[kq * 68 + nq] = tf32r4(v);
        }
        __syncthreads();
        #pragma unroll
        for (int s = 0; s < 8; s++) {
            const int kb = s * 8;
            const int kg = lt * 64 + kb;
            unsigned af[2][4], bf[2][2];
            #pragma unroll
            for (int mf = 0; mf < 2; mf++) {
                int r = wm * 32 + mf * 16 + gid;
                af[mf][0] = __float_as_uint(Ss[r * 260 + kg + tig]);
                af[mf][1] = __float_as_uint(Ss[(r + 8) * 260 + kg + tig]);
                af[mf][2] = __float_as_uint(Ss[r * 260 + kg + tig + 4]);
                af[mf][3] = __float_as_uint(Ss[(r + 8) * 260 + kg + tig + 4]);
            }
            #pragma unroll
            for (int nf = 0; nf < 2; nf++) {
                int n = wn * 16 + nf * 8 + gid;
                bf[nf][0] = __float_as_uint(Wt[(kb + tig) * 68 + n]);
                bf[nf][1] = __float_as_uint(Wt[(kb + tig + 4) * 68 + n]);
            }
            #pragma unroll
            for (int mf = 0; mf < 2; mf++)
                #pragma unroll
                for (int nf = 0; nf < 2; nf++)
                    mma8(oacc[mf][nf], af[mf], bf[nf][0], bf[nf][1]);
        }
    }
    __syncthreads();

    // conv halo tile overlays Ss (PV reads complete)
    {
        const float* vbase = g_v + (long long)bh * SEQ * DH;
        int n0 = st * 64;
        for (int i = tid; i < 96 * 64; i += 256) {
            int r = i >> 6, dh = i & 63;
            int n = n0 + r - 16;
            vt[i] = (n >= 0 && n < SEQ) ? vbase[(long long)n * DH + dh] : 0.f;
        }
    }
    __syncthreads();

    // epilogue: y = O * inv[row] + conv(v)
    float* yb = g_y + (((long long)b * SEQ + st * 64) * NDIM) + h * DH;
    #pragma unroll
    for (int mf = 0; mf < 2; mf++)
        #pragma unroll
        for (int nf = 0; nf < 2; nf++) {
            int r = wm * 32 + mf * 16 + gid;
            int c = wn * 16 + nf * 8 + tig * 2;
            float iv0 = inv[r], iv1 = inv[r + 8];
            float c00 = 0.f, c01 = 0.f, c10 = 0.f, c11 = 0.f;
            #pragma unroll
            for (int t = 0; t < KCONV; t++) {
                float w = wsh[t];
                c00 = fmaf(w, vt[(r + t) * 64 + c], c00);
                c01 = fmaf(w, vt[(r + t) * 64 + c + 1], c01);
                c10 = fmaf(w, vt[(r + 8 + t) * 64 + c], c10);
                c11 = fmaf(w, vt[(r + 8 + t) * 64 + c + 1], c11);
            }
            yb[(long long)r * NDIM + c]           = oacc[mf][nf][0] * iv0 + c00;
            yb[(long long)r * NDIM + c + 1]       = oacc[mf][nf][1] * iv0 + c01;
            yb[(long long)(r + 8) * NDIM + c]     = oacc[mf][nf][2] * iv1 + c10;
            yb[(long long)(r + 8) * NDIM + c + 1] = oacc[mf][nf][3] * iv1 + c11;
        }
}

// ---------------- host orchestration ----------------
static float* sym(const void* p) { void* a = nullptr; cudaGetSymbolAddress(&a, p); return (float*)a; }

extern "C" void kernel_launch(void* const* d_in, const int* in_sizes, int n_in,
                              void* d_out, int out_size)
{
    const float* x      = (const float*)d_in[0];
    const float* w_qkv  = (const float*)d_in[1];
    const float* w_out  = (const float*)d_in[2];
    const float* b_out  = (const float*)d_in[3];
    const float* conv_w = (const float*)d_in[4];
    float* out = (float*)d_out;

    float* p_a2 = sym(g_attn2);
    float* p_z0 = sym(g_z0);
    float* p_z1 = sym(g_z1);
    float* p_xz = sym(g_xz);
    float* p_t  = sym(g_t);
    float* p_u  = sym(g_u);
    float* p_y  = sym(g_y);

    static int attr_done = 0;
    if (!attr_done) {
        cudaFuncSetAttribute(attn2_fused_kernel,  cudaFuncAttributeMaxDynamicSharedMemorySize, 103000);
        cudaFuncSetAttribute(flash_a3v_tc_kernel, cudaFuncAttributeMaxDynamicSharedMemorySize, 88100);
        cudaFuncSetAttribute(attn1_out_tc_kernel, cudaFuncAttributeMaxDynamicSharedMemorySize, 101900);
        attr_done = 1;
    }
    size_t a2_smem = (4352 + 4352 + 16640 + 64) * sizeof(float);     // 101,632
    size_t fl_smem = (21760 + 192) * sizeof(float);                  //  87,808
    size_t a1_smem = (25408 + 40) * sizeof(float);                   // 101,792

    // 1. QKV projection (tensor cores, scatter epilogue)
    tgemm_kernel<2><<<dim3(12, 256, 1), 256>>>(
        x, w_qkv, nullptr, nullptr, 512, 512, 1536, 0,
        0, 0, 0, 1.f, 0.f, nullptr, nullptr);

    // 2. landmark pooling
    pool_kernel<<<2048, 256>>>();

    // 3. attn2 = softmax(ql @ kl^T)
    attn2_fused_kernel<<<dim3(4, BH), 256, a2_smem>>>();

    // 4. pinv init
    pinv_scale_kernel<<<BH, 256>>>();
    zinit_kernel<<<8192, 256>>>();

    // 5. Newton-Schulz iterations (tensor cores, dual-output epilogue)
    float* zc = p_z0;
    float* zn = p_z1;
    for (int it = 0; it < 6; it++) {
        tgemm_kernel<1><<<dim3(2, 2, BH), 256>>>(
            p_a2, zc, p_xz, p_t, 256, 256, 256, 256,
            65536LL, 65536LL, 65536LL, 1.f, 7.f, nullptr, nullptr);
        tgemm_kernel<1><<<dim3(2, 2, BH), 256>>>(
            p_xz, p_t, nullptr, p_u, 256, 256, 256, 256,
            65536LL, 65536LL, 65536LL, 1.f, 15.f, nullptr, nullptr);
        tgemm_kernel<1><<<dim3(2, 2, BH), 256>>>(
            p_xz, p_u, nullptr, p_t, 256, 256, 256, 256,
            65536LL, 65536LL, 65536LL, 1.f, 13.f, nullptr, nullptr);
        tgemm_kernel<1><<<dim3(2, 2, BH), 256>>>(
            zc, p_t, zn, nullptr, 256, 256, 256, 256,
            65536LL, 65536LL, 65536LL, 0.25f, 0.f, nullptr, nullptr);
        float* tmp = zc; zc = zn; zn = tmp;
    }

    // 6. a3v = softmax(ql @ k^T) @ v   (flash, tensor cores)
    flash_a3v_tc_kernel<<<dim3(SPLIT, 4, BH), 256, fl_smem>>>();
    a3v_merge_kernel<<<2048, 256>>>();

    // 7. wm = z @ a3v
    gemm_wm_kernel<<<dim3(1, 4, BH), 256>>>(zc);

    // 8. y = softmax(q @ kl^T) @ wm + conv(v)   (tensor cores, fused conv)
    attn1_out_tc_kernel<<<dim3(128, BH), 256, a1_smem>>>(conv_w);

    // 9. out = y @ w_out + b_out + x   (tensor cores)
    tgemm_kernel<0><<<dim3(4, 256, 1), 256>>>(
        p_y, w_out, out, nullptr, 512, 512, 512, 512,
        0, 0, 0, 1.f, 0.f, b_out, x);
}

// round 7
// speedup vs baseline: 1.4497x; 1.0048x over previous
#include <cuda_runtime.h>

// ---------------- problem constants ----------------
#define BATCH 4
#define SEQ   8192
#define NDIM  512
#define HEADS 8
#define DH    64
#define ML    256          // landmarks
#define LP    32           // tokens per landmark
#define BH    32           // BATCH*HEADS
#define MTOK  32768        // BATCH*SEQ
#define KCONV 33
#define SPLIT 8            // seq split for flash a3v

// ---------------- scratch (device globals; no allocation allowed) ----------------
__device__ float g_q[16777216];      // [BH, SEQ, DH]
__device__ float g_k[16777216];
__device__ float g_v[16777216];
__device__ float g_ql[524288];       // [BH, ML, DH]
__device__ float g_kl[524288];
__device__ float g_attn2[2097152];   // [BH, ML, ML]
__device__ float g_z0[2097152];
__device__ float g_z1[2097152];
__device__ float g_xz[2097152];
__device__ float g_t[2097152];
__device__ float g_u[2097152];
__device__ float g_a3v[524288];      // [BH, ML, DH]
__device__ float g_wm[524288];       // [BH, ML, DH]
__device__ float g_y[16777216];      // [MTOK, NDIM]  (b, n, h*64+dh)
__device__ float g_part_o[4194304];  // [SPLIT][BH*ML][DH]
__device__ float g_part_m[65536];    // [SPLIT][BH*ML]
__device__ float g_part_s[65536];
__device__ float g_scal[2] = {0.f, 0.f};   // atomicMax idempotent across replays

// ================= helpers =================
__device__ __forceinline__ float tf32r(float f)
{
    unsigned u;
    asm("cvt.rna.tf32.f32 %0, %1;" : "=r"(u) : "f"(f));
    return __uint_as_float(u);
}
__device__ __forceinline__ float4 tf32r4(float4 v)
{
    float4 w;
    w.x = tf32r(v.x); w.y = tf32r(v.y); w.z = tf32r(v.z); w.w = tf32r(v.w);
    return w;
}
#define CVT4INPLACE(p) do { float4 _v = *(float4*)(p); *(float4*)(p) = tf32r4(_v); } while (0)

__device__ __forceinline__ void cp16(void* s, const void* g)
{
    unsigned sa = (unsigned)__cvta_generic_to_shared(s);
    asm volatile("cp.async.cg.shared.global [%0], [%1], 16;" :: "r"(sa), "l"(g));
}
__device__ __forceinline__ void cp_commit() { asm volatile("cp.async.commit_group;"); }
__device__ __forceinline__ void cp_wait0()  { asm volatile("cp.async.wait_group 0;"); }
__device__ __forceinline__ void cp_wait1()  { asm volatile("cp.async.wait_group 1;"); }

__device__ __forceinline__ void mma8(float* c, const unsigned* a, unsigned b0, unsigned b1)
{
    asm volatile("mma.sync.aligned.m16n8k8.row.col.f32.tf32.tf32.f32 "
                 "{%0,%1,%2,%3},{%4,%5,%6,%7},{%8,%9},{%0,%1,%2,%3};"
                 : "+f"(c[0]), "+f"(c[1]), "+f"(c[2]), "+f"(c[3])
                 : "r"(a[0]), "r"(a[1]), "r"(a[2]), "r"(a[3]), "r"(b0), "r"(b1));
}

// ================= TF32 tensor-core GEMM, cp.async double-buffered + RNA pass =====
// Block tile 128x128, 256 thr (8 warps = 4Mx2N), warp tile 32x64. K mult of 16.
template<int EPI>
__global__ void __launch_bounds__(256, 2) tgemm_kernel(
    const float* __restrict__ A, const float* __restrict__ B,
    float* __restrict__ C, float* __restrict__ D,
    int K, int lda, int ldb, int ldc,
    long long sA, long long sB, long long sC,
    float alpha, float diag,
    const float* __restrict__ bias, const float* __restrict__ resid)
{
    __shared__ float As[2][128][20];
    __shared__ float Bs[2][16][136];

    int bz = blockIdx.z;
    A += bz * sA;
    B += bz * sB;

    const int m0 = blockIdx.y * 128;
    const int n0 = blockIdx.x * 128;
    const int tid = threadIdx.x;
    const int warp = tid >> 5, lane = tid & 31;
    const int gid = lane >> 2, tig = lane & 3;
    const int wm = warp >> 1, wn = warp & 1;

    const int a_row = tid >> 2, a_kq = (tid & 3) << 2;
    const int b_row = tid >> 5, b_nq = (tid & 31) << 2;

    float acc[2][8][4] = {};

    // prologue stage buf 0
    cp16(&As[0][a_row][a_kq],      &A[(long long)(m0 + a_row) * lda + a_kq]);
    cp16(&As[0][a_row + 64][a_kq], &A[(long long)(m0 + a_row + 64) * lda + a_kq]);
    cp16(&Bs[0][b_row][b_nq],      &B[(long long)b_row * ldb + n0 + b_nq]);
    cp16(&Bs[0][b_row + 8][b_nq],  &B[(long long)(b_row + 8) * ldb + n0 + b_nq]);
    cp_commit();

    int buf = 0;
    for (int k0 = 0; k0 < K; k0 += 16, buf ^= 1) {
        if (k0 + 16 < K) {
            int kn = k0 + 16;
            cp16(&As[buf ^ 1][a_row][a_kq],      &A[(long long)(m0 + a_row) * lda + kn + a_kq]);
            cp16(&As[buf ^ 1][a_row + 64][a_kq], &A[(long long)(m0 + a_row + 64) * lda + kn + a_kq]);
            cp16(&Bs[buf ^ 1][b_row][b_nq],      &B[(long long)(kn + b_row) * ldb + n0 + b_nq]);
            cp16(&Bs[buf ^ 1][b_row + 8][b_nq],  &B[(long long)(kn + b_row + 8) * ldb + n0 + b_nq]);
            cp_commit();
            cp_wait1();
        } else {
            cp_wait0();
        }
        __syncthreads();
        // RNA-convert the staged tiles in place (each thread converts what it staged)
        CVT4INPLACE(&As[buf][a_row][a_kq]);
        CVT4INPLACE(&As[buf][a_row + 64][a_kq]);
        CVT4INPLACE(&Bs[buf][b_row][b_nq]);
        CVT4INPLACE(&Bs[buf][b_row + 8][b_nq]);
        __syncthreads();

        #pragma unroll
        for (int s = 0; s < 2; s++) {
            const int kb = s * 8;
            unsigned af[2][4], bf[8][2];
            #pragma unroll
            for (int mf = 0; mf < 2; mf++) {
                int r = wm * 32 + mf * 16 + gid;
                af[mf][0] = __float_as_uint(As[buf][r][kb + tig]);
                af[mf][1] = __float_as_uint(As[buf][r + 8][kb + tig]);
                af[mf][2] = __float_as_uint(As[buf][r][kb + tig + 4]);
                af[mf][3] = __float_as_uint(As[buf][r + 8][kb + tig + 4]);
            }
            #pragma unroll
            for (int nf = 0; nf < 8; nf++) {
                int c = wn * 64 + nf * 8 + gid;
                bf[nf][0] = __float_as_uint(Bs[buf][kb + tig][c]);
                bf[nf][1] = __float_as_uint(Bs[buf][kb + tig + 4][c]);
            }
            #pragma unroll
            for (int mf = 0; mf < 2; mf++)
                #pragma unroll
                for (int nf = 0; nf < 8; nf++)
                    mma8(acc[mf][nf], af[mf], bf[nf][0], bf[nf][1]);
        }
        __syncthreads();
    }

    #pragma unroll
    for (int mf = 0; mf < 2; mf++) {
        #pragma unroll
        for (int nf = 0; nf < 8; nf++) {
            int r0 = m0 + wm * 32 + mf * 16 + gid;
            int c0 = n0 + wn * 64 + nf * 8 + tig * 2;
            float v00 = alpha * acc[mf][nf][0];
            float v01 = alpha * acc[mf][nf][1];
            float v10 = alpha * acc[mf][nf][2];
            float v11 = alpha * acc[mf][nf][3];

            if (EPI == 0) {
                long long o0 = (long long)r0 * ldc + c0;
                long long o1 = (long long)(r0 + 8) * ldc + c0;
                if (bias)  { v00 += bias[c0]; v01 += bias[c0 + 1]; v10 += bias[c0]; v11 += bias[c0 + 1]; }
                if (resid) { v00 += resid[o0]; v01 += resid[o0 + 1]; v10 += resid[o1]; v11 += resid[o1 + 1]; }
                C[o0] = v00; C[o0 + 1] = v01;
                C[o1] = v10; C[o1 + 1] = v11;
            } else if (EPI == 1) {
                long long o0 = bz * sC + (long long)r0 * ldc + c0;
                long long o1 = bz * sC + (long long)(r0 + 8) * ldc + c0;
                if (C) { C[o0] = v00; C[o0 + 1] = v01; C[o1] = v10; C[o1 + 1] = v11; }
                if (D) {
                    D[o0]     = (r0 == c0         ? diag : 0.f) - v00;
                    D[o0 + 1] = (r0 == c0 + 1     ? diag : 0.f) - v01;
                    D[o1]     = (r0 + 8 == c0     ? diag : 0.f) - v10;
                    D[o1 + 1] = (r0 + 8 == c0 + 1 ? diag : 0.f) - v11;
                }
            } else {
                int sec = c0 >> 9;
                int rem = c0 & 511;
                int h = rem >> 6, dh = rem & 63;
                #pragma unroll
                for (int rr = 0; rr < 2; rr++) {
                    int gm = r0 + rr * 8;
                    int b = gm >> 13, n = gm & 8191;
                    long long off = (((long long)(b * HEADS + h)) * SEQ + n) * DH + dh;
                    float a0 = rr ? v10 : v00;
                    float a1 = rr ? v11 : v01;
                    if (sec == 0)      { g_q[off] = a0 * 0.125f; g_q[off + 1] = a1 * 0.125f; }
                    else if (sec == 1) { g_k[off] = a0;          g_k[off + 1] = a1; }
                    else               { g_v[off] = a0;          g_v[off + 1] = a1; }
                }
            }
        }
    }
}

// ---------------- small SIMT GEMM: wm = z @ a3v ----------------
__global__ void gemm_wm_kernel(const float* __restrict__ Zc)
{
    int bz = blockIdx.z;
    const float* A = Zc + (long long)bz * 65536;
    const float* B = g_a3v + (long long)bz * ML * DH;
    float* C = g_wm + (long long)bz * ML * DH;

    __shared__ float As[16][68];
    __shared__ float Bs[16][68];

    const int tid = threadIdx.x;
    const int tx = tid & 15, ty = tid >> 4;
    const int m0 = blockIdx.y * 64;

    float acc[4][4] = {};
    for (int k0 = 0; k0 < ML; k0 += 16) {
        #pragma unroll
        for (int i = tid; i < 1024; i += 256) {
            int m = i >> 4, kk = i & 15;
            As[kk][m] = A[(m0 + m) * ML + k0 + kk];
        }
        #pragma unroll
        for (int i = tid; i < 1024; i += 256) {
            int kk = i >> 6, n = i & 63;
            Bs[kk][n] = B[(k0 + kk) * DH + n];
        }
        __syncthreads();
        #pragma unroll
        for (int kk = 0; kk < 16; kk++) {
            float a[4], bb[4];
            #pragma unroll
            for (int i = 0; i < 4; i++) a[i] = As[kk][ty * 4 + i];
            #pragma unroll
            for (int j = 0; j < 4; j++) bb[j] = Bs[kk][tx * 4 + j];
            #pragma unroll
            for (int i = 0; i < 4; i++)
                #pragma unroll
                for (int j = 0; j < 4; j++)
                    acc[i][j] = fmaf(a[i], bb[j], acc[i][j]);
        }
        __syncthreads();
    }
    #pragma unroll
    for (int i = 0; i < 4; i++)
        #pragma unroll
        for (int j = 0; j < 4; j++)
            C[(m0 + ty * 4 + i) * DH + tx * 4 + j] = acc[i][j];
}

// ---------------- landmark mean pooling ----------------
__global__ void pool_kernel()
{
    long long idx = (long long)blockIdx.x * 256 + threadIdx.x;
    if (idx >= 524288LL) return;
    int dh = idx & 63;
    int mi = (int)((idx >> 6) & 255);
    int bh = (int)(idx >> 14);
    const float* q = g_q + ((long long)bh * SEQ + mi * LP) * DH + dh;
    const float* k = g_k + ((long long)bh * SEQ + mi * LP) * DH + dh;
    float sq = 0.f, sk = 0.f;
    #pragma unroll
    for (int j = 0; j < LP; j++) { sq += q[j * DH]; sk += k[j * DH]; }
    g_ql[idx] = sq * (1.f / LP);
    g_kl[idx] = sk * (1.f / LP);
}

// ---------------- fused attn2 = softmax(ql @ kl^T) (SIMT, tiny) ------------
__global__ void attn2_fused_kernel()
{
    extern __shared__ float sm[];
    float* QsT = sm;            // [64][68]
    float* Bt  = sm + 4352;     // [64][68]
    float* Lg  = sm + 8704;     // [64][260]
    float* inv = sm + 8704 + 16640;  // [64]

    int mt = blockIdx.x;
    int bh = blockIdx.y;
    int tid = threadIdx.x;
    int tx = tid & 15, ty = tid >> 4;

    const float* qlb = g_ql + ((long long)bh * ML + mt * 64) * DH;
    const float* klb = g_kl + (long long)bh * ML * DH;

    for (int i = tid; i < 4096; i += 256) {
        int row = i >> 6, dh = i & 63;
        QsT[dh * 68 + row] = qlb[row * 64 + dh];
    }

    for (int lt = 0; lt < 4; lt++) {
        __syncthreads();
        for (int i = tid; i < 4096; i += 256) {
            int n = i >> 6, dh = i & 63;
            Bt[dh * 68 + n] = klb[(lt * 64 + n) * 64 + dh];
        }
        __syncthreads();
        float s2[4][4] = {};
        #pragma unroll
        for (int kk = 0; kk < 64; kk++) {
            float a[4], b[4];
            #pragma unroll
            for (int i = 0; i < 4; i++) a[i] = QsT[kk * 68 + ty * 4 + i];
            #pragma unroll
            for (int j = 0; j < 4; j++) b[j] = Bt[kk * 68 + tx * 4 + j];
            #pragma unroll
            for (int i = 0; i < 4; i++)
                #pragma unroll
                for (int j = 0; j < 4; j++)
                    s2[i][j] = fmaf(a[i], b[j], s2[i][j]);
        }
        #pragma unroll
        for (int i = 0; i < 4; i++)
            #pragma unroll
            for (int j = 0; j < 4; j++)
                Lg[(ty * 4 + i) * 260 + lt * 64 + tx * 4 + j] = s2[i][j];
    }
    __syncthreads();

    {
        int r = tid >> 2, c0 = (tid & 3) * 64;
        float mx = -1e30f;
        for (int c = 0; c < 64; c++) mx = fmaxf(mx, Lg[r * 260 + c0 + c]);
        mx = fmaxf(mx, __shfl_xor_sync(0xffffffffu, mx, 1));
        mx = fmaxf(mx, __shfl_xor_sync(0xffffffffu, mx, 2));
        float sum = 0.f;
        for (int c = 0; c < 64; c++) {
            float e = __expf(Lg[r * 260 + c0 + c] - mx);
            Lg[r * 260 + c0 + c] = e;
            sum += e;
        }
        sum += __shfl_xor_sync(0xffffffffu, sum, 1);
        sum += __shfl_xor_sync(0xffffffffu, sum, 2);
        if ((tid & 3) == 0) inv[r] = 1.f / sum;
    }
    __syncthreads();

    float* ob = g_attn2 + ((long long)bh * ML + mt * 64) * ML;
    for (int i = tid; i < 16384; i += 256) {
        int row = i >> 8, col = i & 255;
        ob[row * 256 + col] = Lg[row * 260 + col] * inv[row];
    }
}

// ---------------- pinv scale (column sums only; softmax row-sums == 1) ----
__global__ void pinv_scale_kernel()
{
    int bz = blockIdx.x;
    int j = threadIdx.x;
    const float* p = g_attn2 + (long long)bz * 65536;
    float cs = 0.f;
    #pragma unroll 8
    for (int i = 0; i < 256; i++) cs += p[i * 256 + j];   // coalesced
    atomicMax((int*)&g_scal[0], __float_as_int(cs));
}

__global__ void zinit_kernel()
{
    long long idx = (long long)blockIdx.x * 256 + threadIdx.x;
    if (idx >= 2097152LL) return;
    float inv = 1.f / g_scal[0];     // row-sum max == 1 (softmax rows)
    int c = (int)(idx & 255);
    int r = (int)((idx >> 8) & 255);
    long long bz = idx >> 16;
    g_z0[idx] = g_attn2[(bz << 16) + ((long long)c << 8) + r] * inv;
}

// ================= flash a3v (tensor cores, cp.async + RNA pass) =================
// grid (SPLIT, 4, BH), 256 thr, 2 blocks/SM. 64 landmark rows x 128-token tiles.
__global__ void __launch_bounds__(256, 2) flash_a3v_tc_kernel()
{
    extern __shared__ float sm[];
    float* Qs  = sm;                 // [64][68]
    float* Ks  = sm + 4352;          // [128][68] (overlaid by Ss after QK)
    float* Ss  = sm + 4352;          // [64][132]
    float* Vs  = sm + 13056;         // [128][68]
    float* msh = sm + 21760;
    float* ssh = msh + 64;
    float* fsh = ssh + 64;

    int ks   = blockIdx.x;
    int mt   = blockIdx.y;
    int bh   = blockIdx.z;
    int tid  = threadIdx.x;
    int warp = tid >> 5, lane = tid & 31;
    int gid  = lane >> 2, tig = lane & 3;
    int wm   = warp >> 2, wn = warp & 3;       // 2 x 4 warps

    const float* qlb = g_ql + ((long long)bh * ML + mt * 64) * DH;
    // Q staged synchronously with RNA (once per block)
    for (int i = tid; i < 1024; i += 256) {
        int row = i >> 4, kq = (i & 15) << 2;
        float4 v = *(const float4*)&qlb[row * 64 + kq];
        *(float4*)&Qs[row * 68 + kq] = tf32r4(v);
    }
    if (tid < 64) { msh[tid] = -1e30f; ssh[tid] = 0.f; }

    float oacc[2][2][4] = {};
    const float* kb0 = g_k + (long long)bh * SEQ * DH;
    const float* vb0 = g_v + (long long)bh * SEQ * DH;
    int n_beg = ks * (SEQ / SPLIT);

    for (int nt = 0; nt < SEQ / SPLIT; nt += 128) {
        const float* kp = kb0 + (long long)(n_beg + nt) * DH;
        const float* vp = vb0 + (long long)(n_beg + nt) * DH;
        __syncthreads();                       // prior PV reads of Ss/Vs done
        for (int i = tid; i < 2048; i += 256) {
            int t = i >> 4, kq = (i & 15) << 2;
            cp16(&Ks[t * 68 + kq], &kp[t * 64 + kq]);
            cp16(&Vs[t * 68 + kq], &vp[t * 64 + kq]);
        }
        cp_commit();
        cp_wait0();
        __syncthreads();
        // RNA-convert staged K,V in place
        for (int i = tid; i < 2048; i += 256) {
            int t = i >> 4, kq = (i & 15) << 2;
            CVT4INPLACE(&Ks[t * 68 + kq]);
            CVT4INPLACE(&Vs[t * 68 + kq]);
        }
        __syncthreads();

        // S[64x128] = Q @ K^T   (warp tile 32x32)
        float sacc[2][4][4] = {};
        #pragma unroll
        for (int s = 0; s < 8; s++) {
            const int kb = s * 8;
            unsigned af[2][4], bf[4][2];
            #pragma unroll
            for (int mf = 0; mf < 2; mf++) {
                int r = wm * 32 + mf * 16 + gid;
                af[mf][0] = __float_as_uint(Qs[r * 68 + kb + tig]);
                af[mf][1] = __float_as_uint(Qs[(r + 8) * 68 + kb + tig]);
                af[mf][2] = __float_as_uint(Qs[r * 68 + kb + tig + 4]);
                af[mf][3] = __float_as_uint(Qs[(r + 8) * 68 + kb + tig + 4]);
            }
            #pragma unroll
            for (int nf = 0; nf < 4; nf++) {
                int n = wn * 32 + nf * 8 + gid;
                bf[nf][0] = __float_as_uint(Ks[n * 68 + kb + tig]);
                bf[nf][1] = __float_as_uint(Ks[n * 68 + kb + tig + 4]);
            }
            #pragma unroll
            for (int mf = 0; mf < 2; mf++)
                #pragma unroll
                for (int nf = 0; nf < 4; nf++)
                    mma8(sacc[mf][nf], af[mf], bf[nf][0], bf[nf][1]);
        }
        __syncthreads();                        // Ks reads complete; Ss overlay safe

        #pragma unroll
        for (int mf = 0; mf < 2; mf++)
            #pragma unroll
            for (int nf = 0; nf < 4; nf++) {
                int r = wm * 32 + mf * 16 + gid;
                int c = wn * 32 + nf * 8 + tig * 2;
                Ss[r * 132 + c]           = sacc[mf][nf][0];
                Ss[r * 132 + c + 1]       = sacc[mf][nf][1];
                Ss[(r + 8) * 132 + c]     = sacc[mf][nf][2];
                Ss[(r + 8) * 132 + c + 1] = sacc[mf][nf][3];
            }
        __syncthreads();

        // online softmax: 4 threads/row, float4 over 32 cols each; P stored tf32 (RNA)
        {
            int r = tid >> 2;
            float4* rp = (float4*)&Ss[r * 132 + (tid & 3) * 32];
            float mx = -1e30f;
            #pragma unroll
            for (int i = 0; i < 8; i++) {
                float4 v = rp[i];
                mx = fmaxf(mx, fmaxf(fmaxf(v.x, v.y), fmaxf(v.z, v.w)));
            }
            mx = fmaxf(mx, __shfl_xor_sync(0xffffffffu, mx, 1));
            mx = fmaxf(mx, __shfl_xor_sync(0xffffffffu, mx, 2));
            float mold = msh[r];
            float mnew = fmaxf(mold, mx);
            float sum = 0.f;
            #pragma unroll
            for (int i = 0; i < 8; i++) {
                float4 v = rp[i];
                v.x = __expf(v.x - mnew); v.y = __expf(v.y - mnew);
                v.z = __expf(v.z - mnew); v.w = __expf(v.w - mnew);
                sum += (v.x + v.y) + (v.z + v.w);
                rp[i] = tf32r4(v);
            }
            sum += __shfl_xor_sync(0xffffffffu, sum, 1);
            sum += __shfl_xor_sync(0xffffffffu, sum, 2);
            if ((tid & 3) == 0) {
                float f = __expf(mold - mnew);
                ssh[r] = ssh[r] * f + sum;
                msh[r] = mnew;
                fsh[r] = f;
            }
        }
        __syncthreads();

        // oacc = oacc * f(row) + P @ V   (warp tile 32x16, K=128)
        #pragma unroll
        for (int mf = 0; mf < 2; mf++) {
            int r = wm * 32 + mf * 16 + gid;
            float f0 = fsh[r], f1 = fsh[r + 8];
            #pragma unroll
            for (int nf = 0; nf < 2; nf++) {
                oacc[mf][nf][0] *= f0; oacc[mf][nf][1] *= f0;
                oacc[mf][nf][2] *= f1; oacc[mf][nf][3] *= f1;
            }
        }
        #pragma unroll
        for (int s = 0; s < 16; s++) {
            const int kb = s * 8;
            unsigned af[2][4], bf[2][2];
            #pragma unroll
            for (int mf = 0; mf < 2; mf++) {
                int r = wm * 32 + mf * 16 + gid;
                af[mf][0] = __float_as_uint(Ss[r * 132 + kb + tig]);
                af[mf][1] = __float_as_uint(Ss[(r + 8) * 132 + kb + tig]);
                af[mf][2] = __float_as_uint(Ss[r * 132 + kb + tig + 4]);
                af[mf][3] = __float_as_uint(Ss[(r + 8) * 132 + kb + tig + 4]);
            }
            #pragma unroll
            for (int nf = 0; nf < 2; nf++) {
                int n = wn * 16 + nf * 8 + gid;
                bf[nf][0] = __float_as_uint(Vs[(kb + tig) * 68 + n]);
                bf[nf][1] = __float_as_uint(Vs[(kb + tig + 4) * 68 + n]);
            }
            #pragma unroll
            for (int mf = 0; mf < 2; mf++)
                #pragma unroll
                for (int nf = 0; nf < 2; nf++)
                    mma8(oacc[mf][nf], af[mf], bf[nf][0], bf[nf][1]);
        }
    }
    __syncthreads();

    float* po = g_part_o + (((long long)ks * BH + bh) * ML + mt * 64) * DH;
    #pragma unroll
    for (int mf = 0; mf < 2; mf++)
        #pragma unroll
        for (int nf = 0; nf < 2; nf++) {
            int r = wm * 32 + mf * 16 + gid;
            int c = wn * 16 + nf * 8 + tig * 2;
            po[r * 64 + c]           = oacc[mf][nf][0];
            po[r * 64 + c + 1]       = oacc[mf][nf][1];
            po[(r + 8) * 64 + c]     = oacc[mf][nf][2];
            po[(r + 8) * 64 + c + 1] = oacc[mf][nf][3];
        }
    if (tid < 64) {
        long long ro = ((long long)ks * BH + bh) * ML + mt * 64 + tid;
        g_part_m[ro] = msh[tid];
        g_part_s[ro] = ssh[tid];
    }
}

// ---------------- merge flash partials into a3v ----------------
__global__ void a3v_merge_kernel()
{
    long long idx = (long long)blockIdx.x * 256 + threadIdx.x;
    if (idx >= 524288LL) return;
    int dh = (int)(idx & 63);
    long long row = idx >> 6;
    float M = -1e30f;
    #pragma unroll
    for (int k = 0; k < SPLIT; k++) M = fmaxf(M, g_part_m[k * 8192 + row]);
    float num = 0.f, den = 0.f;
    #pragma unroll
    for (int k = 0; k < SPLIT; k++) {
        float w = __expf(g_part_m[k * 8192 + row] - M);
        num += g_part_o[(k * 8192 + row) * 64 + dh] * w;
        den += g_part_s[k * 8192 + row] * w;
    }
    g_a3v[idx] = num / den;
}

// ================= attn1 path (tensor cores, cp.async + RNA) + fused conv =========
__global__ void __launch_bounds__(256, 2) attn1_out_tc_kernel(const float* __restrict__ convw)
{
    extern __shared__ float sm[];
    float* Qs  = sm;                 // [64][68]  (overlaid by Wt)
    float* Wt  = sm;                 // overlay: [64 k][68] wm chunk
    float* Bs  = sm + 4352;          // [64][68]
    float* Ss  = sm + 8704;          // [64][260] (overlaid by vt)
    float* vt  = sm + 8704;          // overlay: [96][64] conv halo
    float* inv = sm + 25344;
    float* wsh = sm + 25408;

    int st   = blockIdx.x;
    int bh   = blockIdx.y;
    int b    = bh >> 3, h = bh & 7;
    int tid  = threadIdx.x;
    int warp = tid >> 5, lane = tid & 31;
    int gid  = lane >> 2, tig = lane & 3;
    int wm   = warp >> 2, wn = warp & 3;   // 2 x 4 warps

    const float* qb  = g_q  + ((long long)bh * SEQ + st * 64) * DH;
    const float* klb = g_kl + (long long)bh * ML * DH;
    const float* wmb = g_wm + (long long)bh * ML * DH;

    // Q staged synchronously with RNA
    for (int i = tid; i < 1024; i += 256) {
        int row = i >> 4, kq = (i & 15) << 2;
        float4 v = *(const float4*)&qb[row * 64 + kq];
        *(float4*)&Qs[row * 68 + kq] = tf32r4(v);
    }
    if (tid < KCONV) wsh[tid] = convw[h * KCONV + tid];

    // S[64x256] = Q @ KL^T  (4 chunks of 64 landmarks; warp tile 32x16)
    for (int lt = 0; lt < 4; lt++) {
        __syncthreads();
        for (int i = tid; i < 1024; i += 256) {
            int n = i >> 4, kq = (i & 15) << 2;
            cp16(&Bs[n * 68 + kq], &klb[(lt * 64 + n) * 64 + kq]);
        }
        cp_commit();
        cp_wait0();
        __syncthreads();
        for (int i = tid; i < 1024; i += 256) {
            int n = i >> 4, kq = (i & 15) << 2;
            CVT4INPLACE(&Bs[n * 68 + kq]);
        }
        __syncthreads();
        float sacc[2][2][4] = {};
        #pragma unroll
        for (int s = 0; s < 8; s++) {
            const int kb = s * 8;
            unsigned af[2][4], bf[2][2];
            #pragma unroll
            for (int mf = 0; mf < 2; mf++) {
                int r = wm * 32 + mf * 16 + gid;
                af[mf][0] = __float_as_uint(Qs[r * 68 + kb + tig]);
                af[mf][1] = __float_as_uint(Qs[(r + 8) * 68 + kb + tig]);
                af[mf][2] = __float_as_uint(Qs[r * 68 + kb + tig + 4]);
                af[mf][3] = __float_as_uint(Qs[(r + 8) * 68 + kb + tig + 4]);
            }
            #pragma unroll
            for (int nf = 0; nf < 2; nf++) {
                int n = wn * 16 + nf * 8 + gid;
                bf[nf][0] = __float_as_uint(Bs[n * 68 + kb + tig]);
                bf[nf][1] = __float_as_uint(Bs[n * 68 + kb + tig + 4]);
            }
            #pragma unroll
            for (int mf = 0; mf < 2; mf++)
                #pragma unroll
                for (int nf = 0; nf < 2; nf++)
                    mma8(sacc[mf][nf], af[mf], bf[nf][0], bf[nf][1]);
        }
        #pragma unroll
        for (int mf = 0; mf < 2; mf++)
            #pragma unroll
            for (int nf = 0; nf < 2; nf++) {
                int r = wm * 32 + mf * 16 + gid;
                int c = lt * 64 + wn * 16 + nf * 8 + tig * 2;
                Ss[r * 260 + c]           = sacc[mf][nf][0];
                Ss[r * 260 + c + 1]       = sacc[mf][nf][1];
                Ss[(r + 8) * 260 + c]     = sacc[mf][nf][2];
                Ss[(r + 8) * 260 + c + 1] = sacc[mf][nf][3];
            }
    }
    __syncthreads();

    // softmax rows (256 wide, float4); P stored tf32 (RNA); 1/sum applied at epilogue
    {
        int r = tid >> 2;
        float4* rp = (float4*)&Ss[r * 260 + (tid & 3) * 64];
        float mx = -1e30f;
        #pragma unroll
        for (int i = 0; i < 16; i++) {
            float4 v = rp[i];
            mx = fmaxf(mx, fmaxf(fmaxf(v.x, v.y), fmaxf(v.z, v.w)));
        }
        mx = fmaxf(mx, __shfl_xor_sync(0xffffffffu, mx, 1));
        mx = fmaxf(mx, __shfl_xor_sync(0xffffffffu, mx, 2));
        float sum = 0.f;
        #pragma unroll
        for (int i = 0; i < 16; i++) {
            float4 v = rp[i];
            v.x = __expf(v.x - mx); v.y = __expf(v.y - mx);
            v.z = __expf(v.z - mx); v.w = __expf(v.w - mx);
            sum += (v.x + v.y) + (v.z + v.w);
            rp[i] = tf32r4(v);
        }
        sum += __shfl_xor_sync(0xffffffffu, sum, 1);
        sum += __shfl_xor_sync(0xffffffffu, sum, 2);
        if ((tid & 3) == 0) inv[r] = 1.f / sum;
    }
    __syncthreads();

    // O[64x64] = P @ wm  (4 k-chunks; Wt overlays Qs)
    float oacc[2][2][4] = {};
    for (int lt = 0; lt < 4; lt++) {
        __syncthreads();
        for (int i = tid; i < 1024; i += 256) {
            int kq = i >> 4, nq = (i & 15) << 2;
            cp16(&Wt[kq * 68 + nq], &wmb[(lt * 64 + kq) * 64 + nq]);
        }
        cp_commit();
        cp_wait0();
        __syncthreads();
        for (int i = tid; i < 1024; i += 256) {
            int kq = i >> 4, nq = (i & 15) << 2;
            CVT4INPLACE(&Wt[kq * 68 + nq]);
        }
        __syncthreads();
        #pragma unroll
        for (int s = 0; s < 8; s++) {
            const int kb = s * 8;
            const int kg = lt * 64 + kb;
            unsigned af[2][4], bf[2][2];
            #pragma unroll
            for (int mf = 0; mf < 2; mf++) {
                int r = wm * 32 + mf * 16 + gid;
                af[mf][0] = __float_as_uint(Ss[r * 260 + kg + tig]);
                af[mf][1] = __float_as_uint(Ss[(r + 8) * 260 + kg + tig]);
                af[mf][2] = __float_as_uint(Ss[r * 260 + kg + tig + 4]);
                af[mf][3] = __float_as_uint(Ss[(r + 8) * 260 + kg + tig + 4]);
            }
            #pragma unroll
            for (int nf = 0; nf < 2; nf++) {
                int n = wn * 16 + nf * 8 + gid;
                bf[nf][0] = __float_as_uint(Wt[(kb + tig) * 68 + n]);
                bf[nf][1] = __float_as_uint(Wt[(kb + tig + 4) * 68 + n]);
            }
            #pragma unroll
            for (int mf = 0; mf < 2; mf++)
                #pragma unroll
                for (int nf = 0; nf < 2; nf++)
                    mma8(oacc[mf][nf], af[mf], bf[nf][0], bf[nf][1]);
        }
    }
    __syncthreads();

    // conv halo tile overlays Ss (PV reads complete)
    {
        const float* vbase = g_v + (long long)bh * SEQ * DH;
        int n0 = st * 64;
        for (int i = tid; i < 96 * 64; i += 256) {
            int r = i >> 6, dh = i & 63;
            int n = n0 + r - 16;
            vt[i] = (n >= 0 && n < SEQ) ? vbase[(long long)n * DH + dh] : 0.f;
        }
    }
    __syncthreads();

    // epilogue: y = O * inv[row] + conv(v)
    float* yb = g_y + (((long long)b * SEQ + st * 64) * NDIM) + h * DH;
    #pragma unroll
    for (int mf = 0; mf < 2; mf++)
        #pragma unroll
        for (int nf = 0; nf < 2; nf++) {
            int r = wm * 32 + mf * 16 + gid;
            int c = wn * 16 + nf * 8 + tig * 2;
            float iv0 = inv[r], iv1 = inv[r + 8];
            float c00 = 0.f, c01 = 0.f, c10 = 0.f, c11 = 0.f;
            #pragma unroll
            for (int t = 0; t < KCONV; t++) {
                float w = wsh[t];
                c00 = fmaf(w, vt[(r + t) * 64 + c], c00);
                c01 = fmaf(w, vt[(r + t) * 64 + c + 1], c01);
                c10 = fmaf(w, vt[(r + 8 + t) * 64 + c], c10);
                c11 = fmaf(w, vt[(r + 8 + t) * 64 + c + 1], c11);
            }
            yb[(long long)r * NDIM + c]           = oacc[mf][nf][0] * iv0 + c00;
            yb[(long long)r * NDIM + c + 1]       = oacc[mf][nf][1] * iv0 + c01;
            yb[(long long)(r + 8) * NDIM + c]     = oacc[mf][nf][2] * iv1 + c10;
            yb[(long long)(r + 8) * NDIM + c + 1] = oacc[mf][nf][3] * iv1 + c11;
        }
}

// ---------------- host orchestration ----------------
static float* sym(const void* p) { void* a = nullptr; cudaGetSymbolAddress(&a, p); return (float*)a; }

extern "C" void kernel_launch(void* const* d_in, const int* in_sizes, int n_in,
                              void* d_out, int out_size)
{
    const float* x      = (const float*)d_in[0];
    const float* w_qkv  = (const float*)d_in[1];
    const float* w_out  = (const float*)d_in[2];
    const float* b_out  = (const float*)d_in[3];
    const float* conv_w = (const float*)d_in[4];
    float* out = (float*)d_out;

    float* p_a2 = sym(g_attn2);
    float* p_z0 = sym(g_z0);
    float* p_z1 = sym(g_z1);
    float* p_xz = sym(g_xz);
    float* p_t  = sym(g_t);
    float* p_u  = sym(g_u);
    float* p_y  = sym(g_y);

    static int attr_done = 0;
    if (!attr_done) {
        cudaFuncSetAttribute(attn2_fused_kernel,  cudaFuncAttributeMaxDynamicSharedMemorySize, 103000);
        cudaFuncSetAttribute(flash_a3v_tc_kernel, cudaFuncAttributeMaxDynamicSharedMemorySize, 88100);
        cudaFuncSetAttribute(attn1_out_tc_kernel, cudaFuncAttributeMaxDynamicSharedMemorySize, 101900);
        attr_done = 1;
    }
    size_t a2_smem = (4352 + 4352 + 16640 + 64) * sizeof(float);     // 101,632
    size_t fl_smem = (21760 + 192) * sizeof(float);                  //  87,808
    size_t a1_smem = (25408 + 40) * sizeof(float);                   // 101,792

    // 1. QKV projection (tensor cores, scatter epilogue)
    tgemm_kernel<2><<<dim3(12, 256, 1), 256>>>(
        x, w_qkv, nullptr, nullptr, 512, 512, 1536, 0,
        0, 0, 0, 1.f, 0.f, nullptr, nullptr);

    // 2. landmark pooling
    pool_kernel<<<2048, 256>>>();

    // 3. attn2 = softmax(ql @ kl^T)
    attn2_fused_kernel<<<dim3(4, BH), 256, a2_smem>>>();

    // 4. pinv init
    pinv_scale_kernel<<<BH, 256>>>();
    zinit_kernel<<<8192, 256>>>();

    // 5. Newton-Schulz iterations (tensor cores, dual-output epilogue)
    float* zc = p_z0;
    float* zn = p_z1;
    for (int it = 0; it < 6; it++) {
        tgemm_kernel<1><<<dim3(2, 2, BH), 256>>>(
            p_a2, zc, p_xz, p_t, 256, 256, 256, 256,
            65536LL, 65536LL, 65536LL, 1.f, 7.f, nullptr, nullptr);
        tgemm_kernel<1><<<dim3(2, 2, BH), 256>>>(
            p_xz, p_t, nullptr, p_u, 256, 256, 256, 256,
            65536LL, 65536LL, 65536LL, 1.f, 15.f, nullptr, nullptr);
        tgemm_kernel<1><<<dim3(2, 2, BH), 256>>>(
            p_xz, p_u, nullptr, p_t, 256, 256, 256, 256,
            65536LL, 65536LL, 65536LL, 1.f, 13.f, nullptr, nullptr);
        tgemm_kernel<1><<<dim3(2, 2, BH), 256>>>(
            zc, p_t, zn, nullptr, 256, 256, 256, 256,
            65536LL, 65536LL, 65536LL, 0.25f, 0.f, nullptr, nullptr);
        float* tmp = zc; zc = zn; zn = tmp;
    }

    // 6. a3v = softmax(ql @ k^T) @ v   (flash, tensor cores)
    flash_a3v_tc_kernel<<<dim3(SPLIT, 4, BH), 256, fl_smem>>>();
    a3v_merge_kernel<<<2048, 256>>>();

    // 7. wm = z @ a3v
    gemm_wm_kernel<<<dim3(1, 4, BH), 256>>>(zc);

    // 8. y = softmax(q @ kl^T) @ wm + conv(v)   (tensor cores, fused conv)
    attn1_out_tc_kernel<<<dim3(128, BH), 256, a1_smem>>>(conv_w);

    // 9. out = y @ w_out + b_out + x   (tensor cores)
    tgemm_kernel<0><<<dim3(4, 256, 1), 256>>>(
        p_y, w_out, out, nullptr, 512, 512, 512, 512,
        0, 0, 0, 1.f, 0.f, b_out, x);
}

// round 8
// speedup vs baseline: 1.6025x; 1.1054x over previous
#include <cuda_runtime.h>

// ---------------- problem constants ----------------
#define BATCH 4
#define SEQ   8192
#define NDIM  512
#define HEADS 8
#define DH    64
#define ML    256
#define LP    32
#define BH    32
#define MTOK  32768
#define KCONV 33
#define SPLIT 8
#define PINV_BLOCKS 128

// ---------------- scratch ----------------
__device__ float g_q[16777216];      // [BH, SEQ, DH]  (tf32-rounded, q pre-scaled)
__device__ float g_k[16777216];      // tf32-rounded
__device__ float g_v[16777216];      // tf32-rounded
__device__ float g_ql[524288];       // tf32-rounded
__device__ float g_kl[524288];       // tf32-rounded
__device__ float g_attn2[2097152];   // tf32-rounded
__device__ float g_z0[2097152];      // tf32-rounded
__device__ float g_z1[2097152];
__device__ float g_xz[2097152];
__device__ float g_t[2097152];
__device__ float g_u[2097152];
__device__ float g_a3v[524288];
__device__ float g_wm[524288];       // tf32-rounded
__device__ float g_y[16777216];      // tf32-rounded
__device__ float g_part_o[4194304];
__device__ float g_part_m[65536];
__device__ float g_part_s[65536];
__device__ float g_csp[65536];       // [bz*8+rc][256] partial col sums
__device__ float g_scal[2] = {0.f, 0.f};
__device__ unsigned g_bar_count = 0;
__device__ volatile unsigned g_bar_gen = 0;

// ================= helpers =================
__device__ __forceinline__ float tf32r(float f)
{
    unsigned u;
    asm("cvt.rna.tf32.f32 %0, %1;" : "=r"(u) : "f"(f));
    return __uint_as_float(u);
}
__device__ __forceinline__ float4 tf32r4(float4 v)
{
    float4 w;
    w.x = tf32r(v.x); w.y = tf32r(v.y); w.z = tf32r(v.z); w.w = tf32r(v.w);
    return w;
}
#define CVT4INPLACE(p) do { float4 _v = *(float4*)(p); *(float4*)(p) = tf32r4(_v); } while (0)

__device__ __forceinline__ void cp16(void* s, const void* g)
{
    unsigned sa = (unsigned)__cvta_generic_to_shared(s);
    asm volatile("cp.async.cg.shared.global [%0], [%1], 16;" :: "r"(sa), "l"(g));
}
__device__ __forceinline__ void cp_commit() { asm volatile("cp.async.commit_group;"); }
__device__ __forceinline__ void cp_wait0()  { asm volatile("cp.async.wait_group 0;"); }
__device__ __forceinline__ void cp_wait1()  { asm volatile("cp.async.wait_group 1;"); }

__device__ __forceinline__ void mma8(float* c, const unsigned* a, unsigned b0, unsigned b1)
{
    asm volatile("mma.sync.aligned.m16n8k8.row.col.f32.tf32.tf32.f32 "
                 "{%0,%1,%2,%3},{%4,%5,%6,%7},{%8,%9},{%0,%1,%2,%3};"
                 : "+f"(c[0]), "+f"(c[1]), "+f"(c[2]), "+f"(c[3])
                 : "r"(a[0]), "r"(a[1]), "r"(a[2]), "r"(a[3]), "r"(b0), "r"(b1));
}

// software grid barrier: all PINV_BLOCKS blocks guaranteed co-resident
__device__ __forceinline__ void grid_sync_sw()
{
    __syncthreads();
    __threadfence();
    if (threadIdx.x == 0) {
        unsigned gen = g_bar_gen;
        if (atomicAdd(&g_bar_count, 1u) == PINV_BLOCKS - 1) {
            atomicExch(&g_bar_count, 0u);
            __threadfence();
            g_bar_gen = gen + 1;
        } else {
            while (g_bar_gen == gen) __nanosleep(64);
        }
    }
    __syncthreads();
}

// ================= TF32 tensor-core GEMM, cp.async double-buffered =================
// Block tile 128x128, 256 thr (8 warps = 4Mx2N). CVTA/CVTB: RNA-round staged tiles.
// EPI 0: C = alpha*A@B [+bias][+resid]     EPI 2: qkv scatter (rounded stores)
template<int EPI, bool CVTA, bool CVTB>
__global__ void __launch_bounds__(256, 2) tgemm_kernel(
    const float* __restrict__ A, const float* __restrict__ B,
    float* __restrict__ C,
    int K, int lda, int ldb, int ldc,
    float alpha,
    const float* __restrict__ bias, const float* __restrict__ resid)
{
    __shared__ float As[2][128][20];
    __shared__ float Bs[2][16][136];

    const int m0 = blockIdx.y * 128;
    const int n0 = blockIdx.x * 128;
    const int tid = threadIdx.x;
    const int warp = tid >> 5, lane = tid & 31;
    const int gid = lane >> 2, tig = lane & 3;
    const int wm = warp >> 1, wn = warp & 1;

    const int a_row = tid >> 2, a_kq = (tid & 3) << 2;
    const int b_row = tid >> 5, b_nq = (tid & 31) << 2;

    float acc[2][8][4] = {};

    cp16(&As[0][a_row][a_kq],      &A[(long long)(m0 + a_row) * lda + a_kq]);
    cp16(&As[0][a_row + 64][a_kq], &A[(long long)(m0 + a_row + 64) * lda + a_kq]);
    cp16(&Bs[0][b_row][b_nq],      &B[(long long)b_row * ldb + n0 + b_nq]);
    cp16(&Bs[0][b_row + 8][b_nq],  &B[(long long)(b_row + 8) * ldb + n0 + b_nq]);
    cp_commit();

    int buf = 0;
    for (int k0 = 0; k0 < K; k0 += 16, buf ^= 1) {
        if (k0 + 16 < K) {
            int kn = k0 + 16;
            cp16(&As[buf ^ 1][a_row][a_kq],      &A[(long long)(m0 + a_row) * lda + kn + a_kq]);
            cp16(&As[buf ^ 1][a_row + 64][a_kq], &A[(long long)(m0 + a_row + 64) * lda + kn + a_kq]);
            cp16(&Bs[buf ^ 1][b_row][b_nq],      &B[(long long)(kn + b_row) * ldb + n0 + b_nq]);
            cp16(&Bs[buf ^ 1][b_row + 8][b_nq],  &B[(long long)(kn + b_row + 8) * ldb + n0 + b_nq]);
            cp_commit();
            cp_wait1();
        } else {
            cp_wait0();
        }
        __syncthreads();
        if (CVTA || CVTB) {
            if (CVTA) { CVT4INPLACE(&As[buf][a_row][a_kq]); CVT4INPLACE(&As[buf][a_row + 64][a_kq]); }
            if (CVTB) { CVT4INPLACE(&Bs[buf][b_row][b_nq]); CVT4INPLACE(&Bs[buf][b_row + 8][b_nq]); }
            __syncthreads();
        }

        #pragma unroll
        for (int s = 0; s < 2; s++) {
            const int kb = s * 8;
            unsigned af[2][4], bf[8][2];
            #pragma unroll
            for (int mf = 0; mf < 2; mf++) {
                int r = wm * 32 + mf * 16 + gid;
                af[mf][0] = __float_as_uint(As[buf][r][kb + tig]);
                af[mf][1] = __float_as_uint(As[buf][r + 8][kb + tig]);
                af[mf][2] = __float_as_uint(As[buf][r][kb + tig + 4]);
                af[mf][3] = __float_as_uint(As[buf][r + 8][kb + tig + 4]);
            }
            #pragma unroll
            for (int nf = 0; nf < 8; nf++) {
                int c = wn * 64 + nf * 8 + gid;
                bf[nf][0] = __float_as_uint(Bs[buf][kb + tig][c]);
                bf[nf][1] = __float_as_uint(Bs[buf][kb + tig + 4][c]);
            }
            #pragma unroll
            for (int mf = 0; mf < 2; mf++)
                #pragma unroll
                for (int nf = 0; nf < 8; nf++)
                    mma8(acc[mf][nf], af[mf], bf[nf][0], bf[nf][1]);
        }
        __syncthreads();
    }

    #pragma unroll
    for (int mf = 0; mf < 2; mf++) {
        #pragma unroll
        for (int nf = 0; nf < 8; nf++) {
            int r0 = m0 + wm * 32 + mf * 16 + gid;
            int c0 = n0 + wn * 64 + nf * 8 + tig * 2;
            float v00 = alpha * acc[mf][nf][0];
            float v01 = alpha * acc[mf][nf][1];
            float v10 = alpha * acc[mf][nf][2];
            float v11 = alpha * acc[mf][nf][3];

            if (EPI == 0) {
                long long o0 = (long long)r0 * ldc + c0;
                long long o1 = (long long)(r0 + 8) * ldc + c0;
                if (bias)  { v00 += bias[c0]; v01 += bias[c0 + 1]; v10 += bias[c0]; v11 += bias[c0 + 1]; }
                if (resid) { v00 += resid[o0]; v01 += resid[o0 + 1]; v10 += resid[o1]; v11 += resid[o1 + 1]; }
                C[o0] = v00; C[o0 + 1] = v01;
                C[o1] = v10; C[o1 + 1] = v11;
            } else {    // qkv scatter, rounded stores
                int sec = c0 >> 9;
                int rem = c0 & 511;
                int h = rem >> 6, dh = rem & 63;
                #pragma unroll
                for (int rr = 0; rr < 2; rr++) {
                    int gm = r0 + rr * 8;
                    int b = gm >> 13, n = gm & 8191;
                    long long off = (((long long)(b * HEADS + h)) * SEQ + n) * DH + dh;
                    float a0 = rr ? v10 : v00;
                    float a1 = rr ? v11 : v01;
                    if (sec == 0)      { g_q[off] = tf32r(a0 * 0.125f); g_q[off + 1] = tf32r(a1 * 0.125f); }
                    else if (sec == 1) { g_k[off] = tf32r(a0);          g_k[off + 1] = tf32r(a1); }
                    else               { g_v[off] = tf32r(a0);          g_v[off + 1] = tf32r(a1); }
                }
            }
        }
    }
}

// ================= fused Newton-Schulz pinv: 24 GEMM phases, 1 launch =================
// 128 blocks (bz x 2 x 2 tiles). Inputs pre-rounded; no cvt. Outputs stored rounded.
__device__ __forceinline__ void gemm_tile256(
    float* As, float* Bs,                      // smem: As[2][128][20], Bs[2][16][136]
    const float* __restrict__ A, const float* __restrict__ B,
    float* __restrict__ C, float* __restrict__ D,
    float alpha, float diag, int m0, int n0)
{
    const int tid = threadIdx.x;
    const int warp = tid >> 5, lane = tid & 31;
    const int gid = lane >> 2, tig = lane & 3;
    const int wm = warp >> 1, wn = warp & 1;
    const int a_row = tid >> 2, a_kq = (tid & 3) << 2;
    const int b_row = tid >> 5, b_nq = (tid & 31) << 2;

    float acc[2][8][4] = {};

    cp16(&As[(a_row) * 20 + a_kq],        &A[(m0 + a_row) * 256 + a_kq]);
    cp16(&As[(a_row + 64) * 20 + a_kq],   &A[(m0 + a_row + 64) * 256 + a_kq]);
    cp16(&Bs[(b_row) * 136 + b_nq],       &B[b_row * 256 + n0 + b_nq]);
    cp16(&Bs[(b_row + 8) * 136 + b_nq],   &B[(b_row + 8) * 256 + n0 + b_nq]);
    cp_commit();

    int buf = 0;
    for (int k0 = 0; k0 < 256; k0 += 16, buf ^= 1) {
        float* Ab = As + buf * 2560;
        float* Bb = Bs + buf * 2176;
        if (k0 + 16 < 256) {
            int kn = k0 + 16;
            float* An = As + (buf ^ 1) * 2560;
            float* Bn = Bs + (buf ^ 1) * 2176;
            cp16(&An[(a_row) * 20 + a_kq],      &A[(m0 + a_row) * 256 + kn + a_kq]);
            cp16(&An[(a_row + 64) * 20 + a_kq], &A[(m0 + a_row + 64) * 256 + kn + a_kq]);
            cp16(&Bn[(b_row) * 136 + b_nq],     &B[(kn + b_row) * 256 + n0 + b_nq]);
            cp16(&Bn[(b_row + 8) * 136 + b_nq], &B[(kn + b_row + 8) * 256 + n0 + b_nq]);
            cp_commit();
            cp_wait1();
        } else {
            cp_wait0();
        }
        __syncthreads();

        #pragma unroll
        for (int s = 0; s < 2; s++) {
            const int kb = s * 8;
            unsigned af[2][4], bf[8][2];
            #pragma unroll
            for (int mf = 0; mf < 2; mf++) {
                int r = wm * 32 + mf * 16 + gid;
                af[mf][0] = __float_as_uint(Ab[r * 20 + kb + tig]);
                af[mf][1] = __float_as_uint(Ab[(r + 8) * 20 + kb + tig]);
                af[mf][2] = __float_as_uint(Ab[r * 20 + kb + tig + 4]);
                af[mf][3] = __float_as_uint(Ab[(r + 8) * 20 + kb + tig + 4]);
            }
            #pragma unroll
            for (int nf = 0; nf < 8; nf++) {
                int c = wn * 64 + nf * 8 + gid;
                bf[nf][0] = __float_as_uint(Bb[(kb + tig) * 136 + c]);
                bf[nf][1] = __float_as_uint(Bb[(kb + tig + 4) * 136 + c]);
            }
            #pragma unroll
            for (int mf = 0; mf < 2; mf++)
                #pragma unroll
                for (int nf = 0; nf < 8; nf++)
                    mma8(acc[mf][nf], af[mf], bf[nf][0], bf[nf][1]);
        }
        __syncthreads();
    }

    #pragma unroll
    for (int mf = 0; mf < 2; mf++)
        #pragma unroll
        for (int nf = 0; nf < 8; nf++) {
            int r0 = m0 + wm * 32 + mf * 16 + gid;
            int c0 = n0 + wn * 64 + nf * 8 + tig * 2;
            float v00 = alpha * acc[mf][nf][0];
            float v01 = alpha * acc[mf][nf][1];
            float v10 = alpha * acc[mf][nf][2];
            float v11 = alpha * acc[mf][nf][3];
            int o0 = r0 * 256 + c0;
            int o1 = (r0 + 8) * 256 + c0;
            if (C) {
                C[o0] = tf32r(v00); C[o0 + 1] = tf32r(v01);
                C[o1] = tf32r(v10); C[o1 + 1] = tf32r(v11);
            }
            if (D) {
                D[o0]     = tf32r((r0 == c0         ? diag : 0.f) - v00);
                D[o0 + 1] = tf32r((r0 == c0 + 1     ? diag : 0.f) - v01);
                D[o1]     = tf32r((r0 + 8 == c0     ? diag : 0.f) - v10);
                D[o1 + 1] = tf32r((r0 + 8 == c0 + 1 ? diag : 0.f) - v11);
            }
        }
}

__global__ void __launch_bounds__(256, 1) pinv_fused_kernel()
{
    __shared__ float As[2 * 128 * 20];
    __shared__ float Bs[2 * 16 * 136];

    const int bx = blockIdx.x;       // 0..127
    const int bz = bx >> 2;
    const int m0 = ((bx >> 1) & 1) * 128;
    const int n0 = (bx & 1) * 128;

    float* a2 = g_attn2 + bz * 65536;
    float* xz = g_xz + bz * 65536;
    float* tt = g_t  + bz * 65536;
    float* uu = g_u  + bz * 65536;
    float* zc = g_z0 + bz * 65536;
    float* zn = g_z1 + bz * 65536;

    for (int it = 0; it < 6; it++) {
        gemm_tile256(As, Bs, a2, zc, xz, tt, 1.f, 7.f, m0, n0);   // xz = a2@z ; t = 7I - xz
        grid_sync_sw();
        gemm_tile256(As, Bs, xz, tt, nullptr, uu, 1.f, 15.f, m0, n0);  // u = 15I - xz@t
        grid_sync_sw();
        gemm_tile256(As, Bs, xz, uu, nullptr, tt, 1.f, 13.f, m0, n0);  // t = 13I - xz@u
        grid_sync_sw();
        gemm_tile256(As, Bs, zc, tt, zn, nullptr, 0.25f, 0.f, m0, n0); // zn = 0.25 z@t
        grid_sync_sw();
        float* tmp = zc; zc = zn; zn = tmp;
    }
    // after 6 iterations result is back in g_z0
}

// ---------------- small SIMT GEMM: wm = z @ a3v (rounded store) ----------------
__global__ void gemm_wm_kernel()
{
    int bz = blockIdx.z;
    const float* A = g_z0 + (long long)bz * 65536;
    const float* B = g_a3v + (long long)bz * ML * DH;
    float* C = g_wm + (long long)bz * ML * DH;

    __shared__ float As[16][68];
    __shared__ float Bs[16][68];

    const int tid = threadIdx.x;
    const int tx = tid & 15, ty = tid >> 4;
    const int m0 = blockIdx.y * 64;

    float acc[4][4] = {};
    for (int k0 = 0; k0 < ML; k0 += 16) {
        #pragma unroll
        for (int i = tid; i < 1024; i += 256) {
            int m = i >> 4, kk = i & 15;
            As[kk][m] = A[(m0 + m) * ML + k0 + kk];
        }
        #pragma unroll
        for (int i = tid; i < 1024; i += 256) {
            int kk = i >> 6, n = i & 63;
            Bs[kk][n] = B[(k0 + kk) * DH + n];
        }
        __syncthreads();
        #pragma unroll
        for (int kk = 0; kk < 16; kk++) {
            float a[4], bb[4];
            #pragma unroll
            for (int i = 0; i < 4; i++) a[i] = As[kk][ty * 4 + i];
            #pragma unroll
            for (int j = 0; j < 4; j++) bb[j] = Bs[kk][tx * 4 + j];
            #pragma unroll
            for (int i = 0; i < 4; i++)
                #pragma unroll
                for (int j = 0; j < 4; j++)
                    acc[i][j] = fmaf(a[i], bb[j], acc[i][j]);
        }
        __syncthreads();
    }
    #pragma unroll
    for (int i = 0; i < 4; i++)
        #pragma unroll
        for (int j = 0; j < 4; j++)
            C[(m0 + ty * 4 + i) * DH + tx * 4 + j] = tf32r(acc[i][j]);
}

// ---------------- landmark mean pooling (rounded stores) ----------------
__global__ void pool_kernel()
{
    long long idx = (long long)blockIdx.x * 256 + threadIdx.x;
    if (idx >= 524288LL) return;
    int dh = idx & 63;
    int mi = (int)((idx >> 6) & 255);
    int bh = (int)(idx >> 14);
    const float* q = g_q + ((long long)bh * SEQ + mi * LP) * DH + dh;
    const float* k = g_k + ((long long)bh * SEQ + mi * LP) * DH + dh;
    float sq = 0.f, sk = 0.f;
    #pragma unroll
    for (int j = 0; j < LP; j++) { sq += q[j * DH]; sk += k[j * DH]; }
    g_ql[idx] = tf32r(sq * (1.f / LP));
    g_kl[idx] = tf32r(sk * (1.f / LP));
}

// ---------------- fused attn2 = softmax(ql @ kl^T) (SIMT; rounded store) ----
__global__ void attn2_fused_kernel()
{
    extern __shared__ float sm[];
    float* QsT = sm;            // [64][68]
    float* Bt  = sm + 4352;     // [64][68]
    float* Lg  = sm + 8704;     // [64][260]
    float* inv = sm + 8704 + 16640;  // [64]

    int mt = blockIdx.x;
    int bh = blockIdx.y;
    int tid = threadIdx.x;
    int tx = tid & 15, ty = tid >> 4;

    const float* qlb = g_ql + ((long long)bh * ML + mt * 64) * DH;
    const float* klb = g_kl + (long long)bh * ML * DH;

    for (int i = tid; i < 4096; i += 256) {
        int row = i >> 6, dh = i & 63;
        QsT[dh * 68 + row] = qlb[row * 64 + dh];
    }

    for (int lt = 0; lt < 4; lt++) {
        __syncthreads();
        for (int i = tid; i < 4096; i += 256) {
            int n = i >> 6, dh = i & 63;
            Bt[dh * 68 + n] = klb[(lt * 64 + n) * 64 + dh];
        }
        __syncthreads();
        float s2[4][4] = {};
        #pragma unroll
        for (int kk = 0; kk < 64; kk++) {
            float a[4], b[4];
            #pragma unroll
            for (int i = 0; i < 4; i++) a[i] = QsT[kk * 68 + ty * 4 + i];
            #pragma unroll
            for (int j = 0; j < 4; j++) b[j] = Bt[kk * 68 + tx * 4 + j];
            #pragma unroll
            for (int i = 0; i < 4; i++)
                #pragma unroll
                for (int j = 0; j < 4; j++)
                    s2[i][j] = fmaf(a[i], b[j], s2[i][j]);
        }
        #pragma unroll
        for (int i = 0; i < 4; i++)
            #pragma unroll
            for (int j = 0; j < 4; j++)
                Lg[(ty * 4 + i) * 260 + lt * 64 + tx * 4 + j] = s2[i][j];
    }
    __syncthreads();

    {
        int r = tid >> 2, c0 = (tid & 3) * 64;
        float mx = -1e30f;
        for (int c = 0; c < 64; c++) mx = fmaxf(mx, Lg[r * 260 + c0 + c]);
        mx = fmaxf(mx, __shfl_xor_sync(0xffffffffu, mx, 1));
        mx = fmaxf(mx, __shfl_xor_sync(0xffffffffu, mx, 2));
        float sum = 0.f;
        for (int c = 0; c < 64; c++) {
            float e = __expf(Lg[r * 260 + c0 + c] - mx);
            Lg[r * 260 + c0 + c] = e;
            sum += e;
        }
        sum += __shfl_xor_sync(0xffffffffu, sum, 1);
        sum += __shfl_xor_sync(0xffffffffu, sum, 2);
        if ((tid & 3) == 0) inv[r] = 1.f / sum;
    }
    __syncthreads();

    float* ob = g_attn2 + ((long long)bh * ML + mt * 64) * ML;
    for (int i = tid; i < 16384; i += 256) {
        int row = i >> 8, col = i & 255;
        ob[row * 256 + col] = tf32r(Lg[row * 260 + col] * inv[row]);
    }
}

// ---------------- pinv scale: parallel partial col sums + max reduce ----------
__global__ void pinv_scale_part()     // grid (32, 8), 256 thr
{
    int bz = blockIdx.x, rc = blockIdx.y, j = threadIdx.x;
    const float* p = g_attn2 + (long long)bz * 65536 + rc * 32 * 256;
    float cs = 0.f;
    #pragma unroll
    for (int i = 0; i < 32; i++) cs += p[i * 256 + j];
    g_csp[(bz * 8 + rc) * 256 + j] = cs;
}

__global__ void pinv_scale_final()    // grid 32, 256 thr
{
    int bz = blockIdx.x, j = threadIdx.x;
    float cs = 0.f;
    #pragma unroll
    for (int rc = 0; rc < 8; rc++) cs += g_csp[(bz * 8 + rc) * 256 + j];
    atomicMax((int*)&g_scal[0], __float_as_int(cs));   // positive values; idempotent
}

__global__ void zinit_kernel()
{
    long long idx = (long long)blockIdx.x * 256 + threadIdx.x;
    if (idx >= 2097152LL) return;
    float inv = 1.f / g_scal[0];     // row-sum max == 1 (softmax rows)
    int c = (int)(idx & 255);
    int r = (int)((idx >> 8) & 255);
    long long bz = idx >> 16;
    g_z0[idx] = tf32r(g_attn2[(bz << 16) + ((long long)c << 8) + r] * inv);
}

// ================= flash a3v (tensor cores; inputs pre-rounded, no cvt) =========
__global__ void __launch_bounds__(256, 2) flash_a3v_tc_kernel()
{
    extern __shared__ float sm[];
    float* Qs  = sm;                 // [64][68]
    float* Ks  = sm + 4352;          // [128][68] (overlaid by Ss after QK)
    float* Ss  = sm + 4352;          // [64][132]
    float* Vs  = sm + 13056;         // [128][68]
    float* msh = sm + 21760;
    float* ssh = msh + 64;
    float* fsh = ssh + 64;

    int ks   = blockIdx.x;
    int mt   = blockIdx.y;
    int bh   = blockIdx.z;
    int tid  = threadIdx.x;
    int warp = tid >> 5, lane = tid & 31;
    int gid  = lane >> 2, tig = lane & 3;
    int wm   = warp >> 2, wn = warp & 3;       // 2 x 4 warps

    const float* qlb = g_ql + ((long long)bh * ML + mt * 64) * DH;
    for (int i = tid; i < 1024; i += 256) {
        int row = i >> 4, kq = (i & 15) << 2;
        *(float4*)&Qs[row * 68 + kq] = *(const float4*)&qlb[row * 64 + kq];
    }
    if (tid < 64) { msh[tid] = -1e30f; ssh[tid] = 0.f; }

    float oacc[2][2][4] = {};
    const float* kb0 = g_k + (long long)bh * SEQ * DH;
    const float* vb0 = g_v + (long long)bh * SEQ * DH;
    int n_beg = ks * (SEQ / SPLIT);

    for (int nt = 0; nt < SEQ / SPLIT; nt += 128) {
        const float* kp = kb0 + (long long)(n_beg + nt) * DH;
        const float* vp = vb0 + (long long)(n_beg + nt) * DH;
        __syncthreads();
        for (int i = tid; i < 2048; i += 256) {
            int t = i >> 4, kq = (i & 15) << 2;
            cp16(&Ks[t * 68 + kq], &kp[t * 64 + kq]);
            cp16(&Vs[t * 68 + kq], &vp[t * 64 + kq]);
        }
        cp_commit();
        cp_wait0();
        __syncthreads();

        // S[64x128] = Q @ K^T
        float sacc[2][4][4] = {};
        #pragma unroll
        for (int s = 0; s < 8; s++) {
            const int kb = s * 8;
            unsigned af[2][4], bf[4][2];
            #pragma unroll
            for (int mf = 0; mf < 2; mf++) {
                int r = wm * 32 + mf * 16 + gid;
                af[mf][0] = __float_as_uint(Qs[r * 68 + kb + tig]);
                af[mf][1] = __float_as_uint(Qs[(r + 8) * 68 + kb + tig]);
                af[mf][2] = __float_as_uint(Qs[r * 68 + kb + tig + 4]);
                af[mf][3] = __float_as_uint(Qs[(r + 8) * 68 + kb + tig + 4]);
            }
            #pragma unroll
            for (int nf = 0; nf < 4; nf++) {
                int n = wn * 32 + nf * 8 + gid;
                bf[nf][0] = __float_as_uint(Ks[n * 68 + kb + tig]);
                bf[nf][1] = __float_as_uint(Ks[n * 68 + kb + tig + 4]);
            }
            #pragma unroll
            for (int mf = 0; mf < 2; mf++)
                #pragma unroll
                for (int nf = 0; nf < 4; nf++)
                    mma8(sacc[mf][nf], af[mf], bf[nf][0], bf[nf][1]);
        }
        __syncthreads();

        #pragma unroll
        for (int mf = 0; mf < 2; mf++)
            #pragma unroll
            for (int nf = 0; nf < 4; nf++) {
                int r = wm * 32 + mf * 16 + gid;
                int c = wn * 32 + nf * 8 + tig * 2;
                Ss[r * 132 + c]           = sacc[mf][nf][0];
                Ss[r * 132 + c + 1]       = sacc[mf][nf][1];
                Ss[(r + 8) * 132 + c]     = sacc[mf][nf][2];
                Ss[(r + 8) * 132 + c + 1] = sacc[mf][nf][3];
            }
        __syncthreads();

        // online softmax; P stored tf32 (RNA)
        {
            int r = tid >> 2;
            float4* rp = (float4*)&Ss[r * 132 + (tid & 3) * 32];
            float mx = -1e30f;
            #pragma unroll
            for (int i = 0; i < 8; i++) {
                float4 v = rp[i];
                mx = fmaxf(mx, fmaxf(fmaxf(v.x, v.y), fmaxf(v.z, v.w)));
            }
            mx = fmaxf(mx, __shfl_xor_sync(0xffffffffu, mx, 1));
            mx = fmaxf(mx, __shfl_xor_sync(0xffffffffu, mx, 2));
            float mold = msh[r];
            float mnew = fmaxf(mold, mx);
            float sum = 0.f;
            #pragma unroll
            for (int i = 0; i < 8; i++) {
                float4 v = rp[i];
                v.x = __expf(v.x - mnew); v.y = __expf(v.y - mnew);
                v.z = __expf(v.z - mnew); v.w = __expf(v.w - mnew);
                sum += (v.x + v.y) + (v.z + v.w);
                rp[i] = tf32r4(v);
            }
            sum += __shfl_xor_sync(0xffffffffu, sum, 1);
            sum += __shfl_xor_sync(0xffffffffu, sum, 2);
            if ((tid & 3) == 0) {
                float f = __expf(mold - mnew);
                ssh[r] = ssh[r] * f + sum;
                msh[r] = mnew;
                fsh[r] = f;
            }
        }
        __syncthreads();

        // oacc = oacc * f(row) + P @ V
        #pragma unroll
        for (int mf = 0; mf < 2; mf++) {
            int r = wm * 32 + mf * 16 + gid;
            float f0 = fsh[r], f1 = fsh[r + 8];
            #pragma unroll
            for (int nf = 0; nf < 2; nf++) {
                oacc[mf][nf][0] *= f0; oacc[mf][nf][1] *= f0;
                oacc[mf][nf][2] *= f1; oacc[mf][nf][3] *= f1;
            }
        }
        #pragma unroll
        for (int s = 0; s < 16; s++) {
            const int kb = s * 8;
            unsigned af[2][4], bf[2][2];
            #pragma unroll
            for (int mf = 0; mf < 2; mf++) {
                int r = wm * 32 + mf * 16 + gid;
                af[mf][0] = __float_as_uint(Ss[r * 132 + kb + tig]);
                af[mf][1] = __float_as_uint(Ss[(r + 8) * 132 + kb + tig]);
                af[mf][2] = __float_as_uint(Ss[r * 132 + kb + tig + 4]);
                af[mf][3] = __float_as_uint(Ss[(r + 8) * 132 + kb + tig + 4]);
            }
            #pragma unroll
            for (int nf = 0; nf < 2; nf++) {
                int n = wn * 16 + nf * 8 + gid;
                bf[nf][0] = __float_as_uint(Vs[(kb + tig) * 68 + n]);
                bf[nf][1] = __float_as_uint(Vs[(kb + tig + 4) * 68 + n]);
            }
            #pragma unroll
            for (int mf = 0; mf < 2; mf++)
                #pragma unroll
                for (int nf = 0; nf < 2; nf++)
                    mma8(oacc[mf][nf], af[mf], bf[nf][0], bf[nf][1]);
        }
    }
    __syncthreads();

    float* po = g_part_o + (((long long)ks * BH + bh) * ML + mt * 64) * DH;
    #pragma unroll
    for (int mf = 0; mf < 2; mf++)
        #pragma unroll
        for (int nf = 0; nf < 2; nf++) {
            int r = wm * 32 + mf * 16 + gid;
            int c = wn * 16 + nf * 8 + tig * 2;
            po[r * 64 + c]           = oacc[mf][nf][0];
            po[r * 64 + c + 1]       = oacc[mf][nf][1];
            po[(r + 8) * 64 + c]     = oacc[mf][nf][2];
            po[(r + 8) * 64 + c + 1] = oacc[mf][nf][3];
        }
    if (tid < 64) {
        long long ro = ((long long)ks * BH + bh) * ML + mt * 64 + tid;
        g_part_m[ro] = msh[tid];
        g_part_s[ro] = ssh[tid];
    }
}

// ---------------- merge flash partials into a3v ----------------
__global__ void a3v_merge_kernel()
{
    long long idx = (long long)blockIdx.x * 256 + threadIdx.x;
    if (idx >= 524288LL) return;
    int dh = (int)(idx & 63);
    long long row = idx >> 6;
    float M = -1e30f;
    #pragma unroll
    for (int k = 0; k < SPLIT; k++) M = fmaxf(M, g_part_m[k * 8192 + row]);
    float num = 0.f, den = 0.f;
    #pragma unroll
    for (int k = 0; k < SPLIT; k++) {
        float w = __expf(g_part_m[k * 8192 + row] - M);
        num += g_part_o[(k * 8192 + row) * 64 + dh] * w;
        den += g_part_s[k * 8192 + row] * w;
    }
    g_a3v[idx] = num / den;
}

// ================= attn1 path (inputs pre-rounded; no cvt) + fused conv =========
__global__ void __launch_bounds__(256, 2) attn1_out_tc_kernel(const float* __restrict__ convw)
{
    extern __shared__ float sm[];
    float* Qs  = sm;                 // [64][68]  (overlaid by Wt)
    float* Wt  = sm;                 // overlay: [64 k][68] wm chunk
    float* Bs  = sm + 4352;          // [64][68]
    float* Ss  = sm + 8704;          // [64][260] (overlaid by vt)
    float* vt  = sm + 8704;          // overlay: [96][64] conv halo
    float* inv = sm + 25344;
    float* wsh = sm + 25408;

    int st   = blockIdx.x;
    int bh   = blockIdx.y;
    int b    = bh >> 3, h = bh & 7;
    int tid  = threadIdx.x;
    int warp = tid >> 5, lane = tid & 31;
    int gid  = lane >> 2, tig = lane & 3;
    int wm   = warp >> 2, wn = warp & 3;   // 2 x 4 warps

    const float* qb  = g_q  + ((long long)bh * SEQ + st * 64) * DH;
    const float* klb = g_kl + (long long)bh * ML * DH;
    const float* wmb = g_wm + (long long)bh * ML * DH;

    for (int i = tid; i < 1024; i += 256) {
        int row = i >> 4, kq = (i & 15) << 2;
        *(float4*)&Qs[row * 68 + kq] = *(const float4*)&qb[row * 64 + kq];
    }
    if (tid < KCONV) wsh[tid] = convw[h * KCONV + tid];

    // S[64x256] = Q @ KL^T
    for (int lt = 0; lt < 4; lt++) {
        __syncthreads();
        for (int i = tid; i < 1024; i += 256) {
            int n = i >> 4, kq = (i & 15) << 2;
            cp16(&Bs[n * 68 + kq], &klb[(lt * 64 + n) * 64 + kq]);
        }
        cp_commit();
        cp_wait0();
        __syncthreads();
        float sacc[2][2][4] = {};
        #pragma unroll
        for (int s = 0; s < 8; s++) {
            const int kb = s * 8;
            unsigned af[2][4], bf[2][2];
            #pragma unroll
            for (int mf = 0; mf < 2; mf++) {
                int r = wm * 32 + mf * 16 + gid;
                af[mf][0] = __float_as_uint(Qs[r * 68 + kb + tig]);
                af[mf][1] = __float_as_uint(Qs[(r + 8) * 68 + kb + tig]);
                af[mf][2] = __float_as_uint(Qs[r * 68 + kb + tig + 4]);
                af[mf][3] = __float_as_uint(Qs[(r + 8) * 68 + kb + tig + 4]);
            }
            #pragma unroll
            for (int nf = 0; nf < 2; nf++) {
                int n = wn * 16 + nf * 8 + gid;
                bf[nf][0] = __float_as_uint(Bs[n * 68 + kb + tig]);
                bf[nf][1] = __float_as_uint(Bs[n * 68 + kb + tig + 4]);
            }
            #pragma unroll
            for (int mf = 0; mf < 2; mf++)
                #pragma unroll
                for (int nf = 0; nf < 2; nf++)
                    mma8(sacc[mf][nf], af[mf], bf[nf][0], bf[nf][1]);
        }
        #pragma unroll
        for (int mf = 0; mf < 2; mf++)
            #pragma unroll
            for (int nf = 0; nf < 2; nf++) {
                int r = wm * 32 + mf * 16 + gid;
                int c = lt * 64 + wn * 16 + nf * 8 + tig * 2;
                Ss[r * 260 + c]           = sacc[mf][nf][0];
                Ss[r * 260 + c + 1]       = sacc[mf][nf][1];
                Ss[(r + 8) * 260 + c]     = sacc[mf][nf][2];
                Ss[(r + 8) * 260 + c + 1] = sacc[mf][nf][3];
            }
    }
    __syncthreads();

    // softmax rows; P stored tf32 (RNA); 1/sum at epilogue
    {
        int r = tid >> 2;
        float4* rp = (float4*)&Ss[r * 260 + (tid & 3) * 64];
        float mx = -1e30f;
        #pragma unroll
        for (int i = 0; i < 16; i++) {
            float4 v = rp[i];
            mx = fmaxf(mx, fmaxf(fmaxf(v.x, v.y), fmaxf(v.z, v.w)));
        }
        mx = fmaxf(mx, __shfl_xor_sync(0xffffffffu, mx, 1));
        mx = fmaxf(mx, __shfl_xor_sync(0xffffffffu, mx, 2));
        float sum = 0.f;
        #pragma unroll
        for (int i = 0; i < 16; i++) {
            float4 v = rp[i];
            v.x = __expf(v.x - mx); v.y = __expf(v.y - mx);
            v.z = __expf(v.z - mx); v.w = __expf(v.w - mx);
            sum += (v.x + v.y) + (v.z + v.w);
            rp[i] = tf32r4(v);
        }
        sum += __shfl_xor_sync(0xffffffffu, sum, 1);
        sum += __shfl_xor_sync(0xffffffffu, sum, 2);
        if ((tid & 3) == 0) inv[r] = 1.f / sum;
    }
    __syncthreads();

    // O[64x64] = P @ wm  (Wt overlays Qs; wm pre-rounded)
    float oacc[2][2][4] = {};
    for (int lt = 0; lt < 4; lt++) {
        __syncthreads();
        for (int i = tid; i < 1024; i += 256) {
            int kq = i >> 4, nq = (i & 15) << 2;
            cp16(&Wt[kq * 68 + nq], &wmb[(lt * 64 + kq) * 64 + nq]);
        }
        cp_commit();
        cp_wait0();
        __syncthreads();
        #pragma unroll
        for (int s = 0; s < 8; s++) {
            const int kb = s * 8;
            const int kg = lt * 64 + kb;
            unsigned af[2][4], bf[2][2];
            #pragma unroll
            for (int mf = 0; mf < 2; mf++) {
                int r = wm * 32 + mf * 16 + gid;
                af[mf][0] = __float_as_uint(Ss[r * 260 + kg + tig]);
                af[mf][1] = __float_as_uint(Ss[(r + 8) * 260 + kg + tig]);
                af[mf][2] = __float_as_uint(Ss[r * 260 + kg + tig + 4]);
                af[mf][3] = __float_as_uint(Ss[(r + 8) * 260 + kg + tig + 4]);
            }
            #pragma unroll
            for (int nf = 0; nf < 2; nf++) {
                int n = wn * 16 + nf * 8 + gid;
                bf[nf][0] = __float_as_uint(Wt[(kb + tig) * 68 + n]);
                bf[nf][1] = __float_as_uint(Wt[(kb + tig + 4) * 68 + n]);
            }
            #pragma unroll
            for (int mf = 0; mf < 2; mf++)
                #pragma unroll
                for (int nf = 0; nf < 2; nf++)
                    mma8(oacc[mf][nf], af[mf], bf[nf][0], bf[nf][1]);
        }
    }
    __syncthreads();

    // conv halo tile overlays Ss
    {
        const float* vbase = g_v + (long long)bh * SEQ * DH;
        int n0 = st * 64;
        for (int i = tid; i < 96 * 64; i += 256) {
            int r = i >> 6, dh = i & 63;
            int n = n0 + r - 16;
            vt[i] = (n >= 0 && n < SEQ) ? vbase[(long long)n * DH + dh] : 0.f;
        }
    }
    __syncthreads();

    // epilogue: y = tf32r(O * inv[row] + conv(v))   (pre-rounded for out-proj)
    float* yb = g_y + (((long long)b * SEQ + st * 64) * NDIM) + h * DH;
    #pragma unroll
    for (int mf = 0; mf < 2; mf++)
        #pragma unroll
        for (int nf = 0; nf < 2; nf++) {
            int r = wm * 32 + mf * 16 + gid;
            int c = wn * 16 + nf * 8 + tig * 2;
            float iv0 = inv[r], iv1 = inv[r + 8];
            float c00 = 0.f, c01 = 0.f, c10 = 0.f, c11 = 0.f;
            #pragma unroll
            for (int t = 0; t < KCONV; t++) {
                float w = wsh[t];
                c00 = fmaf(w, vt[(r + t) * 64 + c], c00);
                c01 = fmaf(w, vt[(r + t) * 64 + c + 1], c01);
                c10 = fmaf(w, vt[(r + 8 + t) * 64 + c], c10);
                c11 = fmaf(w, vt[(r + 8 + t) * 64 + c + 1], c11);
            }
            yb[(long long)r * NDIM + c]           = tf32r(oacc[mf][nf][0] * iv0 + c00);
            yb[(long long)r * NDIM + c + 1]       = tf32r(oacc[mf][nf][1] * iv0 + c01);
            yb[(long long)(r + 8) * NDIM + c]     = tf32r(oacc[mf][nf][2] * iv1 + c10);
            yb[(long long)(r + 8) * NDIM + c + 1] = tf32r(oacc[mf][nf][3] * iv1 + c11);
        }
}

// ---------------- host orchestration ----------------
static float* sym(const void* p) { void* a = nullptr; cudaGetSymbolAddress(&a, p); return (float*)a; }

extern "C" void kernel_launch(void* const* d_in, const int* in_sizes, int n_in,
                              void* d_out, int out_size)
{
    const float* x      = (const float*)d_in[0];
    const float* w_qkv  = (const float*)d_in[1];
    const float* w_out  = (const float*)d_in[2];
    const float* b_out  = (const float*)d_in[3];
    const float* conv_w = (const float*)d_in[4];
    float* out = (float*)d_out;

    float* p_y = sym(g_y);

    static int attr_done = 0;
    if (!attr_done) {
        cudaFuncSetAttribute(attn2_fused_kernel,  cudaFuncAttributeMaxDynamicSharedMemorySize, 103000);
        cudaFuncSetAttribute(flash_a3v_tc_kernel, cudaFuncAttributeMaxDynamicSharedMemorySize, 88100);
        cudaFuncSetAttribute(attn1_out_tc_kernel, cudaFuncAttributeMaxDynamicSharedMemorySize, 101900);
        attr_done = 1;
    }
    size_t a2_smem = (4352 + 4352 + 16640 + 64) * sizeof(float);
    size_t fl_smem = (21760 + 192) * sizeof(float);
    size_t a1_smem = (25408 + 40) * sizeof(float);

    // 1. QKV projection (external inputs -> cvt both)
    tgemm_kernel<2, true, true><<<dim3(12, 256, 1), 256>>>(
        x, w_qkv, nullptr, 512, 512, 1536, 0, 1.f, nullptr, nullptr);

    // 2. landmark pooling (rounded)
    pool_kernel<<<2048, 256>>>();

    // 3. attn2 = softmax(ql @ kl^T)   (rounded store)
    attn2_fused_kernel<<<dim3(4, BH), 256, a2_smem>>>();

    // 4. pinv init
    pinv_scale_part<<<dim3(32, 8), 256>>>();
    pinv_scale_final<<<32, 256>>>();
    zinit_kernel<<<8192, 256>>>();

    // 5. Newton-Schulz: single fused kernel, 24 GEMM phases, software grid barrier
    pinv_fused_kernel<<<PINV_BLOCKS, 256>>>();

    // 6. a3v = softmax(ql @ k^T) @ v
    flash_a3v_tc_kernel<<<dim3(SPLIT, 4, BH), 256, fl_smem>>>();
    a3v_merge_kernel<<<2048, 256>>>();

    // 7. wm = z @ a3v   (z in g_z0 after 6 iterations)
    gemm_wm_kernel<<<dim3(1, 4, BH), 256>>>();

    // 8. y = softmax(q @ kl^T) @ wm + conv(v)
    attn1_out_tc_kernel<<<dim3(128, BH), 256, a1_smem>>>(conv_w);

    // 9. out = y @ w_out + b_out + x   (y pre-rounded -> cvt B only)
    tgemm_kernel<0, false, true><<<dim3(4, 256, 1), 256>>>(
        p_y, w_out, out, 512, 512, 512, 512, 1.f, b_out, x);
}

// round 9
// speedup vs baseline: 1.7266x; 1.0775x over previous
#include <cuda_runtime.h>

// ---------------- problem constants ----------------
#define BATCH 4
#define SEQ   8192
#define NDIM  512
#define HEADS 8
#define DH    64
#define ML    256
#define LP    32
#define BH    32
#define MTOK  32768
#define KCONV 33
#define SPLIT 8
#define PINV_BLOCKS 128

// ---------------- scratch ----------------
__device__ float g_q[16777216];      // [BH, SEQ, DH]  tf32-rounded (q pre-scaled)
__device__ float g_k[16777216];      // tf32-rounded
__device__ float g_v[16777216];      // tf32-rounded
__device__ float g_ql[524288];       // tf32-rounded
__device__ float g_kl[524288];       // tf32-rounded
__device__ float g_attn2[2097152];   // (step0: rounded w_qkv) then rounded attn2
__device__ float g_z0[2097152];
__device__ float g_z1[2097152];
__device__ float g_xz[2097152];      // (pinv scratch; later rounded w_out)
__device__ float g_t[2097152];
__device__ float g_u[2097152];
__device__ float g_a3v[524288];
__device__ float g_wm[524288];       // tf32-rounded
__device__ float g_y[16777216];      // (step0: rounded x) then y (rounded)
__device__ float g_part_o[4194304];
__device__ float g_part_m[65536];
__device__ float g_part_s[65536];
__device__ float g_csp[65536];
__device__ float g_scal[2] = {0.f, 0.f};
__device__ unsigned g_bar_count = 0;
__device__ volatile unsigned g_bar_gen = 0;

// ================= helpers =================
__device__ __forceinline__ float tf32r(float f)
{
    unsigned u;
    asm("cvt.rna.tf32.f32 %0, %1;" : "=r"(u) : "f"(f));
    return __uint_as_float(u);
}
__device__ __forceinline__ float4 tf32r4(float4 v)
{
    float4 w;
    w.x = tf32r(v.x); w.y = tf32r(v.y); w.z = tf32r(v.z); w.w = tf32r(v.w);
    return w;
}

__device__ __forceinline__ void cp16(void* s, const void* g)
{
    unsigned sa = (unsigned)__cvta_generic_to_shared(s);
    asm volatile("cp.async.cg.shared.global [%0], [%1], 16;" :: "r"(sa), "l"(g));
}
__device__ __forceinline__ void cp_commit() { asm volatile("cp.async.commit_group;"); }
__device__ __forceinline__ void cp_wait0()  { asm volatile("cp.async.wait_group 0;"); }
__device__ __forceinline__ void cp_wait1()  { asm volatile("cp.async.wait_group 1;"); }

__device__ __forceinline__ void mma8(float* c, const unsigned* a, unsigned b0, unsigned b1)
{
    asm volatile("mma.sync.aligned.m16n8k8.row.col.f32.tf32.tf32.f32 "
                 "{%0,%1,%2,%3},{%4,%5,%6,%7},{%8,%9},{%0,%1,%2,%3};"
                 : "+f"(c[0]), "+f"(c[1]), "+f"(c[2]), "+f"(c[3])
                 : "r"(a[0]), "r"(a[1]), "r"(a[2]), "r"(a[3]), "r"(b0), "r"(b1));
}

// software grid barrier (all PINV_BLOCKS co-resident)
__device__ __forceinline__ void grid_sync_sw()
{
    __syncthreads();
    __threadfence();
    if (threadIdx.x == 0) {
        unsigned gen = g_bar_gen;
        if (atomicAdd(&g_bar_count, 1u) == PINV_BLOCKS - 1) {
            atomicExch(&g_bar_count, 0u);
            __threadfence();
            g_bar_gen = gen + 1;
        } else {
            while (g_bar_gen == gen) __nanosleep(64);
        }
    }
    __syncthreads();
}

// ---------------- tf32 rounding prelude (external inputs) ----------------
__global__ void round_kernel(float* __restrict__ dst, const float* __restrict__ src, int n4)
{
    int i = blockIdx.x * 256 + threadIdx.x;
    if (i < n4) ((float4*)dst)[i] = tf32r4(((const float4*)src)[i]);
}

// ================= TF32 GEMM, 3-stage cp.async, ONE sync per k-iter =============
// Block tile 128x128, 256 thr (8 warps = 4Mx2N). Inputs pre-rounded (no cvt).
// EPI 0: C = alpha*A@B [+bias][+resid]     EPI 2: qkv scatter (rounded stores)
// dynamic smem: As 3*2560 + Bs 3*2176 floats = 56,832 B
template<int EPI>
__global__ void __launch_bounds__(256, 2) tgemm_kernel(
    const float* __restrict__ A, const float* __restrict__ B,
    float* __restrict__ C,
    int K, int lda, int ldb, int ldc,
    float alpha,
    const float* __restrict__ bias, const float* __restrict__ resid)
{
    extern __shared__ float smem[];
    float* As = smem;            // 3 stages of [128][20]
    float* Bs = smem + 7680;     // 3 stages of [16][136]

    const int m0 = blockIdx.y * 128;
    const int n0 = blockIdx.x * 128;
    const int tid = threadIdx.x;
    const int warp = tid >> 5, lane = tid & 31;
    const int gid = lane >> 2, tig = lane & 3;
    const int wm = warp >> 1, wn = warp & 1;

    const int a_row = tid >> 2, a_kq = (tid & 3) << 2;
    const int b_row = tid >> 5, b_nq = (tid & 31) << 2;

    auto stage = [&](int s, int kk) {
        float* Ab = As + s * 2560;
        float* Bb = Bs + s * 2176;
        cp16(&Ab[a_row * 20 + a_kq],        &A[(long long)(m0 + a_row) * lda + kk + a_kq]);
        cp16(&Ab[(a_row + 64) * 20 + a_kq], &A[(long long)(m0 + a_row + 64) * lda + kk + a_kq]);
        cp16(&Bb[b_row * 136 + b_nq],       &B[(long long)(kk + b_row) * ldb + n0 + b_nq]);
        cp16(&Bb[(b_row + 8) * 136 + b_nq], &B[(long long)(kk + b_row + 8) * ldb + n0 + b_nq]);
    };

    float acc[2][8][4] = {};

    stage(0, 0);  cp_commit();
    stage(1, 16); cp_commit();

    int buf = 0;
    for (int k0 = 0; k0 < K; k0 += 16) {
        cp_wait1();
        __syncthreads();
        int kn = k0 + 32;
        int s2 = buf + 2; if (s2 >= 3) s2 -= 3;
        if (kn < K) stage(s2, kn);
        cp_commit();

        float* Ab = As + buf * 2560;
        float* Bb = Bs + buf * 2176;
        #pragma unroll
        for (int s = 0; s < 2; s++) {
            const int kb = s * 8;
            unsigned af[2][4], bf[8][2];
            #pragma unroll
            for (int mf = 0; mf < 2; mf++) {
                int r = wm * 32 + mf * 16 + gid;
                af[mf][0] = __float_as_uint(Ab[r * 20 + kb + tig]);
                af[mf][1] = __float_as_uint(Ab[(r + 8) * 20 + kb + tig]);
                af[mf][2] = __float_as_uint(Ab[r * 20 + kb + tig + 4]);
                af[mf][3] = __float_as_uint(Ab[(r + 8) * 20 + kb + tig + 4]);
            }
            #pragma unroll
            for (int nf = 0; nf < 8; nf++) {
                int c = wn * 64 + nf * 8 + gid;
                bf[nf][0] = __float_as_uint(Bb[(kb + tig) * 136 + c]);
                bf[nf][1] = __float_as_uint(Bb[(kb + tig + 4) * 136 + c]);
            }
            #pragma unroll
            for (int mf = 0; mf < 2; mf++)
                #pragma unroll
                for (int nf = 0; nf < 8; nf++)
                    mma8(acc[mf][nf], af[mf], bf[nf][0], bf[nf][1]);
        }
        buf = (buf + 1 == 3) ? 0 : buf + 1;
    }

    #pragma unroll
    for (int mf = 0; mf < 2; mf++) {
        #pragma unroll
        for (int nf = 0; nf < 8; nf++) {
            int r0 = m0 + wm * 32 + mf * 16 + gid;
            int c0 = n0 + wn * 64 + nf * 8 + tig * 2;
            float v00 = alpha * acc[mf][nf][0];
            float v01 = alpha * acc[mf][nf][1];
            float v10 = alpha * acc[mf][nf][2];
            float v11 = alpha * acc[mf][nf][3];

            if (EPI == 0) {
                long long o0 = (long long)r0 * ldc + c0;
                long long o1 = (long long)(r0 + 8) * ldc + c0;
                if (bias)  { v00 += bias[c0]; v01 += bias[c0 + 1]; v10 += bias[c0]; v11 += bias[c0 + 1]; }
                if (resid) { v00 += resid[o0]; v01 += resid[o0 + 1]; v10 += resid[o1]; v11 += resid[o1 + 1]; }
                C[o0] = v00; C[o0 + 1] = v01;
                C[o1] = v10; C[o1 + 1] = v11;
            } else {
                int sec = c0 >> 9;
                int rem = c0 & 511;
                int h = rem >> 6, dh = rem & 63;
                #pragma unroll
                for (int rr = 0; rr < 2; rr++) {
                    int gm = r0 + rr * 8;
                    int b = gm >> 13, n = gm & 8191;
                    long long off = (((long long)(b * HEADS + h)) * SEQ + n) * DH + dh;
                    float a0 = rr ? v10 : v00;
                    float a1 = rr ? v11 : v01;
                    if (sec == 0)      { g_q[off] = tf32r(a0 * 0.125f); g_q[off + 1] = tf32r(a1 * 0.125f); }
                    else if (sec == 1) { g_k[off] = tf32r(a0);          g_k[off + 1] = tf32r(a1); }
                    else               { g_v[off] = tf32r(a0);          g_v[off + 1] = tf32r(a1); }
                }
            }
        }
    }
}

// ================= fused Newton-Schulz pinv (3-stage, 1 sync/iter) =================
__device__ __forceinline__ void gemm_tile256(
    float* As, float* Bs,
    const float* __restrict__ A, const float* __restrict__ B,
    float* __restrict__ C, float* __restrict__ D,
    float alpha, float diag, int m0, int n0)
{
    const int tid = threadIdx.x;
    const int warp = tid >> 5, lane = tid & 31;
    const int gid = lane >> 2, tig = lane & 3;
    const int wm = warp >> 1, wn = warp & 1;
    const int a_row = tid >> 2, a_kq = (tid & 3) << 2;
    const int b_row = tid >> 5, b_nq = (tid & 31) << 2;

    auto stage = [&](int s, int kk) {
        float* Ab = As + s * 2560;
        float* Bb = Bs + s * 2176;
        cp16(&Ab[a_row * 20 + a_kq],        &A[(m0 + a_row) * 256 + kk + a_kq]);
        cp16(&Ab[(a_row + 64) * 20 + a_kq], &A[(m0 + a_row + 64) * 256 + kk + a_kq]);
        cp16(&Bb[b_row * 136 + b_nq],       &B[(kk + b_row) * 256 + n0 + b_nq]);
        cp16(&Bb[(b_row + 8) * 136 + b_nq], &B[(kk + b_row + 8) * 256 + n0 + b_nq]);
    };

    float acc[2][8][4] = {};

    stage(0, 0);  cp_commit();
    stage(1, 16); cp_commit();

    int buf = 0;
    for (int k0 = 0; k0 < 256; k0 += 16) {
        cp_wait1();
        __syncthreads();
        int kn = k0 + 32;
        int s2 = buf + 2; if (s2 >= 3) s2 -= 3;
        if (kn < 256) stage(s2, kn);
        cp_commit();

        float* Ab = As + buf * 2560;
        float* Bb = Bs + buf * 2176;
        #pragma unroll
        for (int s = 0; s < 2; s++) {
            const int kb = s * 8;
            unsigned af[2][4], bf[8][2];
            #pragma unroll
            for (int mf = 0; mf < 2; mf++) {
                int r = wm * 32 + mf * 16 + gid;
                af[mf][0] = __float_as_uint(Ab[r * 20 + kb + tig]);
                af[mf][1] = __float_as_uint(Ab[(r + 8) * 20 + kb + tig]);
                af[mf][2] = __float_as_uint(Ab[r * 20 + kb + tig + 4]);
                af[mf][3] = __float_as_uint(Ab[(r + 8) * 20 + kb + tig + 4]);
            }
            #pragma unroll
            for (int nf = 0; nf < 8; nf++) {
                int c = wn * 64 + nf * 8 + gid;
                bf[nf][0] = __float_as_uint(Bb[(kb + tig) * 136 + c]);
                bf[nf][1] = __float_as_uint(Bb[(kb + tig + 4) * 136 + c]);
            }
            #pragma unroll
            for (int mf = 0; mf < 2; mf++)
                #pragma unroll
                for (int nf = 0; nf < 8; nf++)
                    mma8(acc[mf][nf], af[mf], bf[nf][0], bf[nf][1]);
        }
        buf = (buf + 1 == 3) ? 0 : buf + 1;
    }

    #pragma unroll
    for (int mf = 0; mf < 2; mf++)
        #pragma unroll
        for (int nf = 0; nf < 8; nf++) {
            int r0 = m0 + wm * 32 + mf * 16 + gid;
            int c0 = n0 + wn * 64 + nf * 8 + tig * 2;
            float v00 = alpha * acc[mf][nf][0];
            float v01 = alpha * acc[mf][nf][1];
            float v10 = alpha * acc[mf][nf][2];
            float v11 = alpha * acc[mf][nf][3];
            int o0 = r0 * 256 + c0;
            int o1 = (r0 + 8) * 256 + c0;
            if (C) {
                C[o0] = tf32r(v00); C[o0 + 1] = tf32r(v01);
                C[o1] = tf32r(v10); C[o1 + 1] = tf32r(v11);
            }
            if (D) {
                D[o0]     = tf32r((r0 == c0         ? diag : 0.f) - v00);
                D[o0 + 1] = tf32r((r0 == c0 + 1     ? diag : 0.f) - v01);
                D[o1]     = tf32r((r0 + 8 == c0     ? diag : 0.f) - v10);
                D[o1 + 1] = tf32r((r0 + 8 == c0 + 1 ? diag : 0.f) - v11);
            }
        }
}

__global__ void __launch_bounds__(256, 1) pinv_fused_kernel()
{
    extern __shared__ float smem[];
    float* As = smem;
    float* Bs = smem + 7680;

    const int bx = blockIdx.x;
    const int bz = bx >> 2;
    const int m0 = ((bx >> 1) & 1) * 128;
    const int n0 = (bx & 1) * 128;

    float* a2 = g_attn2 + bz * 65536;
    float* xz = g_xz + bz * 65536;
    float* tt = g_t  + bz * 65536;
    float* uu = g_u  + bz * 65536;
    float* zc = g_z0 + bz * 65536;
    float* zn = g_z1 + bz * 65536;

    for (int it = 0; it < 6; it++) {
        gemm_tile256(As, Bs, a2, zc, xz, tt, 1.f, 7.f, m0, n0);
        grid_sync_sw();
        gemm_tile256(As, Bs, xz, tt, nullptr, uu, 1.f, 15.f, m0, n0);
        grid_sync_sw();
        gemm_tile256(As, Bs, xz, uu, nullptr, tt, 1.f, 13.f, m0, n0);
        grid_sync_sw();
        gemm_tile256(As, Bs, zc, tt, zn, nullptr, 0.25f, 0.f, m0, n0);
        grid_sync_sw();
        float* tmp = zc; zc = zn; zn = tmp;
    }
}

// ---------------- small SIMT GEMM: wm = z @ a3v (rounded store) ----------------
__global__ void gemm_wm_kernel()
{
    int bz = blockIdx.z;
    const float* A = g_z0 + (long long)bz * 65536;
    const float* B = g_a3v + (long long)bz * ML * DH;
    float* C = g_wm + (long long)bz * ML * DH;

    __shared__ float As[16][68];
    __shared__ float Bs[16][68];

    const int tid = threadIdx.x;
    const int tx = tid & 15, ty = tid >> 4;
    const int m0 = blockIdx.y * 64;

    float acc[4][4] = {};
    for (int k0 = 0; k0 < ML; k0 += 16) {
        #pragma unroll
        for (int i = tid; i < 1024; i += 256) {
            int m = i >> 4, kk = i & 15;
            As[kk][m] = A[(m0 + m) * ML + k0 + kk];
        }
        #pragma unroll
        for (int i = tid; i < 1024; i += 256) {
            int kk = i >> 6, n = i & 63;
            Bs[kk][n] = B[(k0 + kk) * DH + n];
        }
        __syncthreads();
        #pragma unroll
        for (int kk = 0; kk < 16; kk++) {
            float a[4], bb[4];
            #pragma unroll
            for (int i = 0; i < 4; i++) a[i] = As[kk][ty * 4 + i];
            #pragma unroll
            for (int j = 0; j < 4; j++) bb[j] = Bs[kk][tx * 4 + j];
            #pragma unroll
            for (int i = 0; i < 4; i++)
                #pragma unroll
                for (int j = 0; j < 4; j++)
                    acc[i][j] = fmaf(a[i], bb[j], acc[i][j]);
        }
        __syncthreads();
    }
    #pragma unroll
    for (int i = 0; i < 4; i++)
        #pragma unroll
        for (int j = 0; j < 4; j++)
            C[(m0 + ty * 4 + i) * DH + tx * 4 + j] = tf32r(acc[i][j]);
}

// ---------------- landmark mean pooling (rounded stores) ----------------
__global__ void pool_kernel()
{
    long long idx = (long long)blockIdx.x * 256 + threadIdx.x;
    if (idx >= 524288LL) return;
    int dh = idx & 63;
    int mi = (int)((idx >> 6) & 255);
    int bh = (int)(idx >> 14);
    const float* q = g_q + ((long long)bh * SEQ + mi * LP) * DH + dh;
    const float* k = g_k + ((long long)bh * SEQ + mi * LP) * DH + dh;
    float sq = 0.f, sk = 0.f;
    #pragma unroll
    for (int j = 0; j < LP; j++) { sq += q[j * DH]; sk += k[j * DH]; }
    g_ql[idx] = tf32r(sq * (1.f / LP));
    g_kl[idx] = tf32r(sk * (1.f / LP));
}

// ---------------- fused attn2 = softmax(ql @ kl^T) (rounded store) ----------
__global__ void attn2_fused_kernel()
{
    extern __shared__ float sm[];
    float* QsT = sm;
    float* Bt  = sm + 4352;
    float* Lg  = sm + 8704;
    float* inv = sm + 8704 + 16640;

    int mt = blockIdx.x;
    int bh = blockIdx.y;
    int tid = threadIdx.x;
    int tx = tid & 15, ty = tid >> 4;

    const float* qlb = g_ql + ((long long)bh * ML + mt * 64) * DH;
    const float* klb = g_kl + (long long)bh * ML * DH;

    for (int i = tid; i < 4096; i += 256) {
        int row = i >> 6, dh = i & 63;
        QsT[dh * 68 + row] = qlb[row * 64 + dh];
    }

    for (int lt = 0; lt < 4; lt++) {
        __syncthreads();
        for (int i = tid; i < 4096; i += 256) {
            int n = i >> 6, dh = i & 63;
            Bt[dh * 68 + n] = klb[(lt * 64 + n) * 64 + dh];
        }
        __syncthreads();
        float s2[4][4] = {};
        #pragma unroll
        for (int kk = 0; kk < 64; kk++) {
            float a[4], b[4];
            #pragma unroll
            for (int i = 0; i < 4; i++) a[i] = QsT[kk * 68 + ty * 4 + i];
            #pragma unroll
            for (int j = 0; j < 4; j++) b[j] = Bt[kk * 68 + tx * 4 + j];
            #pragma unroll
            for (int i = 0; i < 4; i++)
                #pragma unroll
                for (int j = 0; j < 4; j++)
                    s2[i][j] = fmaf(a[i], b[j], s2[i][j]);
        }
        #pragma unroll
        for (int i = 0; i < 4; i++)
            #pragma unroll
            for (int j = 0; j < 4; j++)
                Lg[(ty * 4 + i) * 260 + lt * 64 + tx * 4 + j] = s2[i][j];
    }
    __syncthreads();

    {
        int r = tid >> 2, c0 = (tid & 3) * 64;
        float mx = -1e30f;
        for (int c = 0; c < 64; c++) mx = fmaxf(mx, Lg[r * 260 + c0 + c]);
        mx = fmaxf(mx, __shfl_xor_sync(0xffffffffu, mx, 1));
        mx = fmaxf(mx, __shfl_xor_sync(0xffffffffu, mx, 2));
        float sum = 0.f;
        for (int c = 0; c < 64; c++) {
            float e = __expf(Lg[r * 260 + c0 + c] - mx);
            Lg[r * 260 + c0 + c] = e;
            sum += e;
        }
        sum += __shfl_xor_sync(0xffffffffu, sum, 1);
        sum += __shfl_xor_sync(0xffffffffu, sum, 2);
        if ((tid & 3) == 0) inv[r] = 1.f / sum;
    }
    __syncthreads();

    float* ob = g_attn2 + ((long long)bh * ML + mt * 64) * ML;
    for (int i = tid; i < 16384; i += 256) {
        int row = i >> 8, col = i & 255;
        ob[row * 256 + col] = tf32r(Lg[row * 260 + col] * inv[row]);
    }
}

// ---------------- pinv scale ----------------
__global__ void pinv_scale_part()
{
    int bz = blockIdx.x, rc = blockIdx.y, j = threadIdx.x;
    const float* p = g_attn2 + (long long)bz * 65536 + rc * 32 * 256;
    float cs = 0.f;
    #pragma unroll
    for (int i = 0; i < 32; i++) cs += p[i * 256 + j];
    g_csp[(bz * 8 + rc) * 256 + j] = cs;
}

__global__ void pinv_scale_final()
{
    int bz = blockIdx.x, j = threadIdx.x;
    float cs = 0.f;
    #pragma unroll
    for (int rc = 0; rc < 8; rc++) cs += g_csp[(bz * 8 + rc) * 256 + j];
    atomicMax((int*)&g_scal[0], __float_as_int(cs));
}

__global__ void zinit_kernel()
{
    long long idx = (long long)blockIdx.x * 256 + threadIdx.x;
    if (idx >= 2097152LL) return;
    float inv = 1.f / g_scal[0];
    int c = (int)(idx & 255);
    int r = (int)((idx >> 8) & 255);
    long long bz = idx >> 16;
    g_z0[idx] = tf32r(g_attn2[(bz << 16) + ((long long)c << 8) + r] * inv);
}

// ================= flash a3v (unchanged from R8) =================
__global__ void __launch_bounds__(256, 2) flash_a3v_tc_kernel()
{
    extern __shared__ float sm[];
    float* Qs  = sm;
    float* Ks  = sm + 4352;
    float* Ss  = sm + 4352;
    float* Vs  = sm + 13056;
    float* msh = sm + 21760;
    float* ssh = msh + 64;
    float* fsh = ssh + 64;

    int ks   = blockIdx.x;
    int mt   = blockIdx.y;
    int bh   = blockIdx.z;
    int tid  = threadIdx.x;
    int warp = tid >> 5, lane = tid & 31;
    int gid  = lane >> 2, tig = lane & 3;
    int wm   = warp >> 2, wn = warp & 3;

    const float* qlb = g_ql + ((long long)bh * ML + mt * 64) * DH;
    for (int i = tid; i < 1024; i += 256) {
        int row = i >> 4, kq = (i & 15) << 2;
        *(float4*)&Qs[row * 68 + kq] = *(const float4*)&qlb[row * 64 + kq];
    }
    if (tid < 64) { msh[tid] = -1e30f; ssh[tid] = 0.f; }

    float oacc[2][2][4] = {};
    const float* kb0 = g_k + (long long)bh * SEQ * DH;
    const float* vb0 = g_v + (long long)bh * SEQ * DH;
    int n_beg = ks * (SEQ / SPLIT);

    for (int nt = 0; nt < SEQ / SPLIT; nt += 128) {
        const float* kp = kb0 + (long long)(n_beg + nt) * DH;
        const float* vp = vb0 + (long long)(n_beg + nt) * DH;
        __syncthreads();
        for (int i = tid; i < 2048; i += 256) {
            int t = i >> 4, kq = (i & 15) << 2;
            cp16(&Ks[t * 68 + kq], &kp[t * 64 + kq]);
            cp16(&Vs[t * 68 + kq], &vp[t * 64 + kq]);
        }
        cp_commit();
        cp_wait0();
        __syncthreads();

        float sacc[2][4][4] = {};
        #pragma unroll
        for (int s = 0; s < 8; s++) {
            const int kb = s * 8;
            unsigned af[2][4], bf[4][2];
            #pragma unroll
            for (int mf = 0; mf < 2; mf++) {
                int r = wm * 32 + mf * 16 + gid;
                af[mf][0] = __float_as_uint(Qs[r * 68 + kb + tig]);
                af[mf][1] = __float_as_uint(Qs[(r + 8) * 68 + kb + tig]);
                af[mf][2] = __float_as_uint(Qs[r * 68 + kb + tig + 4]);
                af[mf][3] = __float_as_uint(Qs[(r + 8) * 68 + kb + tig + 4]);
            }
            #pragma unroll
            for (int nf = 0; nf < 4; nf++) {
                int n = wn * 32 + nf * 8 + gid;
                bf[nf][0] = __float_as_uint(Ks[n * 68 + kb + tig]);
                bf[nf][1] = __float_as_uint(Ks[n * 68 + kb + tig + 4]);
            }
            #pragma unroll
            for (int mf = 0; mf < 2; mf++)
                #pragma unroll
                for (int nf = 0; nf < 4; nf++)
                    mma8(sacc[mf][nf], af[mf], bf[nf][0], bf[nf][1]);
        }
        __syncthreads();

        #pragma unroll
        for (int mf = 0; mf < 2; mf++)
            #pragma unroll
            for (int nf = 0; nf < 4; nf++) {
                int r = wm * 32 + mf * 16 + gid;
                int c = wn * 32 + nf * 8 + tig * 2;
                Ss[r * 132 + c]           = sacc[mf][nf][0];
                Ss[r * 132 + c + 1]       = sacc[mf][nf][1];
                Ss[(r + 8) * 132 + c]     = sacc[mf][nf][2];
                Ss[(r + 8) * 132 + c + 1] = sacc[mf][nf][3];
            }
        __syncthreads();

        {
            int r = tid >> 2;
            float4* rp = (float4*)&Ss[r * 132 + (tid & 3) * 32];
            float mx = -1e30f;
            #pragma unroll
            for (int i = 0; i < 8; i++) {
                float4 v = rp[i];
                mx = fmaxf(mx, fmaxf(fmaxf(v.x, v.y), fmaxf(v.z, v.w)));
            }
            mx = fmaxf(mx, __shfl_xor_sync(0xffffffffu, mx, 1));
            mx = fmaxf(mx, __shfl_xor_sync(0xffffffffu, mx, 2));
            float mold = msh[r];
            float mnew = fmaxf(mold, mx);
            float sum = 0.f;
            #pragma unroll
            for (int i = 0; i < 8; i++) {
                float4 v = rp[i];
                v.x = __expf(v.x - mnew); v.y = __expf(v.y - mnew);
                v.z = __expf(v.z - mnew); v.w = __expf(v.w - mnew);
                sum += (v.x + v.y) + (v.z + v.w);
                rp[i] = tf32r4(v);
            }
            sum += __shfl_xor_sync(0xffffffffu, sum, 1);
            sum += __shfl_xor_sync(0xffffffffu, sum, 2);
            if ((tid & 3) == 0) {
                float f = __expf(mold - mnew);
                ssh[r] = ssh[r] * f + sum;
                msh[r] = mnew;
                fsh[r] = f;
            }
        }
        __syncthreads();

        #pragma unroll
        for (int mf = 0; mf < 2; mf++) {
            int r = wm * 32 + mf * 16 + gid;
            float f0 = fsh[r], f1 = fsh[r + 8];
            #pragma unroll
            for (int nf = 0; nf < 2; nf++) {
                oacc[mf][nf][0] *= f0; oacc[mf][nf][1] *= f0;
                oacc[mf][nf][2] *= f1; oacc[mf][nf][3] *= f1;
            }
        }
        #pragma unroll
        for (int s = 0; s < 16; s++) {
            const int kb = s * 8;
            unsigned af[2][4], bf[2][2];
            #pragma unroll
            for (int mf = 0; mf < 2; mf++) {
                int r = wm * 32 + mf * 16 + gid;
                af[mf][0] = __float_as_uint(Ss[r * 132 + kb + tig]);
                af[mf][1] = __float_as_uint(Ss[(r + 8) * 132 + kb + tig]);
                af[mf][2] = __float_as_uint(Ss[r * 132 + kb + tig + 4]);
                af[mf][3] = __float_as_uint(Ss[(r + 8) * 132 + kb + tig + 4]);
            }
            #pragma unroll
            for (int nf = 0; nf < 2; nf++) {
                int n = wn * 16 + nf * 8 + gid;
                bf[nf][0] = __float_as_uint(Vs[(kb + tig) * 68 + n]);
                bf[nf][1] = __float_as_uint(Vs[(kb + tig + 4) * 68 + n]);
            }
            #pragma unroll
            for (int mf = 0; mf < 2; mf++)
                #pragma unroll
                for (int nf = 0; nf < 2; nf++)
                    mma8(oacc[mf][nf], af[mf], bf[nf][0], bf[nf][1]);
        }
    }
    __syncthreads();

    float* po = g_part_o + (((long long)ks * BH + bh) * ML + mt * 64) * DH;
    #pragma unroll
    for (int mf = 0; mf < 2; mf++)
        #pragma unroll
        for (int nf = 0; nf < 2; nf++) {
            int r = wm * 32 + mf * 16 + gid;
            int c = wn * 16 + nf * 8 + tig * 2;
            po[r * 64 + c]           = oacc[mf][nf][0];
            po[r * 64 + c + 1]       = oacc[mf][nf][1];
            po[(r + 8) * 64 + c]     = oacc[mf][nf][2];
            po[(r + 8) * 64 + c + 1] = oacc[mf][nf][3];
        }
    if (tid < 64) {
        long long ro = ((long long)ks * BH + bh) * ML + mt * 64 + tid;
        g_part_m[ro] = msh[tid];
        g_part_s[ro] = ssh[tid];
    }
}

// ---------------- merge flash partials ----------------
__global__ void a3v_merge_kernel()
{
    long long idx = (long long)blockIdx.x * 256 + threadIdx.x;
    if (idx >= 524288LL) return;
    int dh = (int)(idx & 63);
    long long row = idx >> 6;
    float M = -1e30f;
    #pragma unroll
    for (int k = 0; k < SPLIT; k++) M = fmaxf(M, g_part_m[k * 8192 + row]);
    float num = 0.f, den = 0.f;
    #pragma unroll
    for (int k = 0; k < SPLIT; k++) {
        float w = __expf(g_part_m[k * 8192 + row] - M);
        num += g_part_o[(k * 8192 + row) * 64 + dh] * w;
        den += g_part_s[k * 8192 + row] * w;
    }
    g_a3v[idx] = num / den;
}

// ================= attn1 path + fused conv (unchanged from R8) =================
__global__ void __launch_bounds__(256, 2) attn1_out_tc_kernel(const float* __restrict__ convw)
{
    extern __shared__ float sm[];
    float* Qs  = sm;
    float* Wt  = sm;
    float* Bs  = sm + 4352;
    float* Ss  = sm + 8704;
    float* vt  = sm + 8704;
    float* inv = sm + 25344;
    float* wsh = sm + 25408;

    int st   = blockIdx.x;
    int bh   = blockIdx.y;
    int b    = bh >> 3, h = bh & 7;
    int tid  = threadIdx.x;
    int warp = tid >> 5, lane = tid & 31;
    int gid  = lane >> 2, tig = lane & 3;
    int wm   = warp >> 2, wn = warp & 3;

    const float* qb  = g_q  + ((long long)bh * SEQ + st * 64) * DH;
    const float* klb = g_kl + (long long)bh * ML * DH;
    const float* wmb = g_wm + (long long)bh * ML * DH;

    for (int i = tid; i < 1024; i += 256) {
        int row = i >> 4, kq = (i & 15) << 2;
        *(float4*)&Qs[row * 68 + kq] = *(const float4*)&qb[row * 64 + kq];
    }
    if (tid < KCONV) wsh[tid] = convw[h * KCONV + tid];

    for (int lt = 0; lt < 4; lt++) {
        __syncthreads();
        for (int i = tid; i < 1024; i += 256) {
            int n = i >> 4, kq = (i & 15) << 2;
            cp16(&Bs[n * 68 + kq], &klb[(lt * 64 + n) * 64 + kq]);
        }
        cp_commit();
        cp_wait0();
        __syncthreads();
        float sacc[2][2][4] = {};
        #pragma unroll
        for (int s = 0; s < 8; s++) {
            const int kb = s * 8;
            unsigned af[2][4], bf[2][2];
            #pragma unroll
            for (int mf = 0; mf < 2; mf++) {
                int r = wm * 32 + mf * 16 + gid;
                af[mf][0] = __float_as_uint(Qs[r * 68 + kb + tig]);
                af[mf][1] = __float_as_uint(Qs[(r + 8) * 68 + kb + tig]);
                af[mf][2] = __float_as_uint(Qs[r * 68 + kb + tig + 4]);
                af[mf][3] = __float_as_uint(Qs[(r + 8) * 68 + kb + tig + 4]);
            }
            #pragma unroll
            for (int nf = 0; nf < 2; nf++) {
                int n = wn * 16 + nf * 8 + gid;
                bf[nf][0] = __float_as_uint(Bs[n * 68 + kb + tig]);
                bf[nf][1] = __float_as_uint(Bs[n * 68 + kb + tig + 4]);
            }
            #pragma unroll
            for (int mf = 0; mf < 2; mf++)
                #pragma unroll
                for (int nf = 0; nf < 2; nf++)
                    mma8(sacc[mf][nf], af[mf], bf[nf][0], bf[nf][1]);
        }
        #pragma unroll
        for (int mf = 0; mf < 2; mf++)
            #pragma unroll
            for (int nf = 0; nf < 2; nf++) {
                int r = wm * 32 + mf * 16 + gid;
                int c = lt * 64 + wn * 16 + nf * 8 + tig * 2;
                Ss[r * 260 + c]           = sacc[mf][nf][0];
                Ss[r * 260 + c + 1]       = sacc[mf][nf][1];
                Ss[(r + 8) * 260 + c]     = sacc[mf][nf][2];
                Ss[(r + 8) * 260 + c + 1] = sacc[mf][nf][3];
            }
    }
    __syncthreads();

    {
        int r = tid >> 2;
        float4* rp = (float4*)&Ss[r * 260 + (tid & 3) * 64];
        float mx = -1e30f;
        #pragma unroll
        for (int i = 0; i < 16; i++) {
            float4 v = rp[i];
            mx = fmaxf(mx, fmaxf(fmaxf(v.x, v.y), fmaxf(v.z, v.w)));
        }
        mx = fmaxf(mx, __shfl_xor_sync(0xffffffffu, mx, 1));
        mx = fmaxf(mx, __shfl_xor_sync(0xffffffffu, mx, 2));
        float sum = 0.f;
        #pragma unroll
        for (int i = 0; i < 16; i++) {
            float4 v = rp[i];
            v.x = __expf(v.x - mx); v.y = __expf(v.y - mx);
            v.z = __expf(v.z - mx); v.w = __expf(v.w - mx);
            sum += (v.x + v.y) + (v.z + v.w);
            rp[i] = tf32r4(v);
        }
        sum += __shfl_xor_sync(0xffffffffu, sum, 1);
        sum += __shfl_xor_sync(0xffffffffu, sum, 2);
        if ((tid & 3) == 0) inv[r] = 1.f / sum;
    }
    __syncthreads();

    float oacc[2][2][4] = {};
    for (int lt = 0; lt < 4; lt++) {
        __syncthreads();
        for (int i = tid; i < 1024; i += 256) {
            int kq = i >> 4, nq = (i & 15) << 2;
            cp16(&Wt[kq * 68 + nq], &wmb[(lt * 64 + kq) * 64 + nq]);
        }
        cp_commit();
        cp_wait0();
        __syncthreads();
        #pragma unroll
        for (int s = 0; s < 8; s++) {
            const int kb = s * 8;
            const int kg = lt * 64 + kb;
            unsigned af[2][4], bf[2][2];
            #pragma unroll
            for (int mf = 0; mf < 2; mf++) {
                int r = wm * 32 + mf * 16 + gid;
                af[mf][0] = __float_as_uint(Ss[r * 260 + kg + tig]);
                af[mf][1] = __float_as_uint(Ss[(r + 8) * 260 + kg + tig]);
                af[mf][2] = __float_as_uint(Ss[r * 260 + kg + tig + 4]);
                af[mf][3] = __float_as_uint(Ss[(r + 8) * 260 + kg + tig + 4]);
            }
            #pragma unroll
            for (int nf = 0; nf < 2; nf++) {
                int n = wn * 16 + nf * 8 + gid;
                bf[nf][0] = __float_as_uint(Wt[(kb + tig) * 68 + n]);
                bf[nf][1] = __float_as_uint(Wt[(kb + tig + 4) * 68 + n]);
            }
            #pragma unroll
            for (int mf = 0; mf < 2; mf++)
                #pragma unroll
                for (int nf = 0; nf < 2; nf++)
                    mma8(oacc[mf][nf], af[mf], bf[nf][0], bf[nf][1]);
        }
    }
    __syncthreads();

    {
        const float* vbase = g_v + (long long)bh * SEQ * DH;
        int n0 = st * 64;
        for (int i = tid; i < 96 * 64; i += 256) {
            int r = i >> 6, dh = i & 63;
            int n = n0 + r - 16;
            vt[i] = (n >= 0 && n < SEQ) ? vbase[(long long)n * DH + dh] : 0.f;
        }
    }
    __syncthreads();

    float* yb = g_y + (((long long)b * SEQ + st * 64) * NDIM) + h * DH;
    #pragma unroll
    for (int mf = 0; mf < 2; mf++)
        #pragma unroll
        for (int nf = 0; nf < 2; nf++) {
            int r = wm * 32 + mf * 16 + gid;
            int c = wn * 16 + nf * 8 + tig * 2;
            float iv0 = inv[r], iv1 = inv[r + 8];
            float c00 = 0.f, c01 = 0.f, c10 = 0.f, c11 = 0.f;
            #pragma unroll
            for (int t = 0; t < KCONV; t++) {
                float w = wsh[t];
                c00 = fmaf(w, vt[(r + t) * 64 + c], c00);
                c01 = fmaf(w, vt[(r + t) * 64 + c + 1], c01);
                c10 = fmaf(w, vt[(r + 8 + t) * 64 + c], c10);
                c11 = fmaf(w, vt[(r + 8 + t) * 64 + c + 1], c11);
            }
            yb[(long long)r * NDIM + c]           = tf32r(oacc[mf][nf][0] * iv0 + c00);
            yb[(long long)r * NDIM + c + 1]       = tf32r(oacc[mf][nf][1] * iv0 + c01);
            yb[(long long)(r + 8) * NDIM + c]     = tf32r(oacc[mf][nf][2] * iv1 + c10);
            yb[(long long)(r + 8) * NDIM + c + 1] = tf32r(oacc[mf][nf][3] * iv1 + c11);
        }
}

// ---------------- host orchestration ----------------
static float* sym(const void* p) { void* a = nullptr; cudaGetSymbolAddress(&a, p); return (float*)a; }

extern "C" void kernel_launch(void* const* d_in, const int* in_sizes, int n_in,
                              void* d_out, int out_size)
{
    const float* x      = (const float*)d_in[0];
    const float* w_qkv  = (const float*)d_in[1];
    const float* w_out  = (const float*)d_in[2];
    const float* b_out  = (const float*)d_in[3];
    const float* conv_w = (const float*)d_in[4];
    float* out = (float*)d_out;

    float* p_y  = sym(g_y);
    float* p_a2 = sym(g_attn2);
    float* p_xz = sym(g_xz);

    static int attr_done = 0;
    if (!attr_done) {
        cudaFuncSetAttribute(attn2_fused_kernel,  cudaFuncAttributeMaxDynamicSharedMemorySize, 103000);
        cudaFuncSetAttribute(flash_a3v_tc_kernel, cudaFuncAttributeMaxDynamicSharedMemorySize, 88100);
        cudaFuncSetAttribute(attn1_out_tc_kernel, cudaFuncAttributeMaxDynamicSharedMemorySize, 101900);
        cudaFuncSetAttribute(tgemm_kernel<0>,     cudaFuncAttributeMaxDynamicSharedMemorySize, 57000);
        cudaFuncSetAttribute(tgemm_kernel<2>,     cudaFuncAttributeMaxDynamicSharedMemorySize, 57000);
        cudaFuncSetAttribute(pinv_fused_kernel,   cudaFuncAttributeMaxDynamicSharedMemorySize, 57000);
        attr_done = 1;
    }
    size_t a2_smem = (4352 + 4352 + 16640 + 64) * sizeof(float);
    size_t fl_smem = (21760 + 192) * sizeof(float);
    size_t a1_smem = (25408 + 40) * sizeof(float);
    size_t tg_smem = (3 * 2560 + 3 * 2176) * sizeof(float);   // 56,832

    // 0. pre-round external inputs (x -> g_y, w_qkv -> g_attn2)
    round_kernel<<<16384, 256>>>(p_y, x, 4194304);
    round_kernel<<<768, 256>>>(p_a2, w_qkv, 196608);

    // 1. QKV projection (pre-rounded operands, no cvt)
    tgemm_kernel<2><<<dim3(12, 256, 1), 256, tg_smem>>>(
        p_y, p_a2, nullptr, 512, 512, 1536, 0, 1.f, nullptr, nullptr);

    // 2. landmark pooling
    pool_kernel<<<2048, 256>>>();

    // 3. attn2 = softmax(ql @ kl^T)
    attn2_fused_kernel<<<dim3(4, BH), 256, a2_smem>>>();

    // 4. pinv init
    pinv_scale_part<<<dim3(32, 8), 256>>>();
    pinv_scale_final<<<32, 256>>>();
    zinit_kernel<<<8192, 256>>>();

    // 5. Newton-Schulz (fused, 24 phases, software grid barrier)
    pinv_fused_kernel<<<PINV_BLOCKS, 256, tg_smem>>>();

    // 6. a3v = softmax(ql @ k^T) @ v
    flash_a3v_tc_kernel<<<dim3(SPLIT, 4, BH), 256, fl_smem>>>();
    a3v_merge_kernel<<<2048, 256>>>();

    // 7. wm = z @ a3v
    gemm_wm_kernel<<<dim3(1, 4, BH), 256>>>();

    // 8. y = softmax(q @ kl^T) @ wm + conv(v)
    attn1_out_tc_kernel<<<dim3(128, BH), 256, a1_smem>>>(conv_w);

    // 9. round w_out -> g_xz (free after pinv), then out = y @ w_out + b_out + x
    round_kernel<<<256, 256>>>(p_xz, w_out, 65536);
    tgemm_kernel<0><<<dim3(4, 256, 1), 256, tg_smem>>>(
        p_y, p_xz, out, 512, 512, 512, 512, 1.f, b_out, x);
}